// round 8
// baseline (speedup 1.0000x reference)
#include <cuda_runtime.h>
#include <cuda_fp16.h>
#include <cstdint>

#define B 64
#define F 4
#define M 4096
#define D 1024
#define ITERS 15
#define WPD 16   // 64-bit words per D-dim vector
#define WPM 64   // 64-bit words per M-dim vector
#define FINAL_BUF (ITERS & 1)

// ---------------- device scratch (no allocs allowed) ----------------
__device__ unsigned long long g_cb_bits[F][WPD][M];   // codebook bits over d, [f][word][m] (2 MB)
__device__ unsigned long long g_cbcol[F][D][WPM];     // codebook bits over m, [f][d][word] (2 MB)
__device__ __half             g_G[F][D][D];           // Gram matrix C^T C, exact even ints (8 MB)
__device__ unsigned long long g_in_bits[B][WPD];
__device__ unsigned long long g_est[2][B][F][WPD];    // double-buffered estimates (bit 1 = -1)
__device__ int                g_key[B * F];           // argmax keys (atomicMax)
__device__ int                g_diff[ITERS];          // per-iteration "changed" flags

// ---------------- helpers ----------------
__device__ __forceinline__ unsigned long long pack64(const float* p) {
    unsigned long long w = 0ULL;
    #pragma unroll
    for (int t = 0; t < 16; t++) {
        float4 v = reinterpret_cast<const float4*>(p)[t];
        w |= ((unsigned long long)(v.x < 0.f)) << (4 * t + 0);
        w |= ((unsigned long long)(v.y < 0.f)) << (4 * t + 1);
        w |= ((unsigned long long)(v.z < 0.f)) << (4 * t + 2);
        w |= ((unsigned long long)(v.w < 0.f)) << (4 * t + 3);
    }
    return w;
}

__device__ __forceinline__ void mma16816(float* c,
                                         unsigned a0, unsigned a1, unsigned a2, unsigned a3,
                                         unsigned b0, unsigned b1) {
    asm volatile(
        "mma.sync.aligned.m16n8k16.row.col.f32.f16.f16.f32 "
        "{%0,%1,%2,%3}, {%4,%5,%6,%7}, {%8,%9}, {%0,%1,%2,%3};"
        : "+f"(c[0]), "+f"(c[1]), "+f"(c[2]), "+f"(c[3])
        : "r"(a0), "r"(a1), "r"(a2), "r"(a3), "r"(b0), "r"(b1));
}

__device__ __forceinline__ void mma16832s8(int* c,
                                           unsigned a0, unsigned a1, unsigned a2, unsigned a3,
                                           unsigned b0, unsigned b1) {
    asm volatile(
        "mma.sync.aligned.m16n8k32.row.col.s32.s8.s8.s32 "
        "{%0,%1,%2,%3}, {%4,%5,%6,%7}, {%8,%9}, {%0,%1,%2,%3};"
        : "+r"(c[0]), "+r"(c[1]), "+r"(c[2]), "+r"(c[3])
        : "r"(a0), "r"(a1), "r"(a2), "r"(a3), "r"(b0), "r"(b1));
}

// bits (2 low bits, 1 = negative) -> packed half2 {+-1, +-1}
__device__ __forceinline__ unsigned bits2h2(unsigned bits) {
    return 0x3C003C00u ^ ((bits & 1u) << 15) ^ ((bits & 2u) << 30);
}

// ---------------- packing kernels ----------------
__global__ void k_pack_small(const float* __restrict__ input,
                             const float* __restrict__ est0) {
    int idx = blockIdx.x * 256 + threadIdx.x;
    const int base = B * WPD + B * F * WPD;
    if (idx < B * WPD) {
        int b = idx >> 4, j = idx & 15;
        g_in_bits[b][j] = pack64(input + b * D + j * 64);
    } else if (idx < base) {
        int w = idx - B * WPD;
        int b = w >> 6, f = (w >> 4) & 3, j = w & 15;
        g_est[0][b][f][j] = pack64(est0 + (size_t)(b * F + f) * D + j * 64);
    } else if (idx < base + ITERS) {
        g_diff[idx - base] = 0;
    } else if (idx < base + ITERS + B * F) {
        g_key[idx - base - ITERS] = -1;
    }
}

__global__ void k_pack_cb(const float* __restrict__ cb) {
    int idx = blockIdx.x * 256 + threadIdx.x;   // F*WPD*M total
    int m = idx & (M - 1);
    int j = (idx >> 12) & 15;
    int f = idx >> 16;
    g_cb_bits[f][j][m] = pack64(cb + ((size_t)(f * M + m)) * D + j * 64);
}

// ---------------- bit transpose: g_cb_bits (d-words over m) -> g_cbcol (m-words over d) ----
// grid = (F, M/64), block = 256 (8 warps).
__global__ void __launch_bounds__(256) k_transpose_bits() {
    __shared__ unsigned long long sm[64][17];   // [m_local][jd]
    int f  = blockIdx.x;
    int jm = blockIdx.y;       // which m-word (64 m's)
    int tid = threadIdx.x;
    #pragma unroll
    for (int r = 0; r < 4; r++) {
        int idx = tid + 256 * r;       // 1024 words
        int m = idx & 63, j = idx >> 6;
        sm[m][j] = g_cb_bits[f][j][jm * 64 + m];
    }
    __syncthreads();
    int wid = tid >> 5, lane = tid & 31;
    for (int i = 0; i < 128; i++) {
        int d = wid * 128 + i;
        int j = d >> 6, bp = d & 63;
        unsigned lo = __ballot_sync(0xffffffffu,
            (unsigned)((sm[lane][j] >> bp) & 1ULL));
        unsigned hi = __ballot_sync(0xffffffffu,
            (unsigned)((sm[lane + 32][j] >> bp) & 1ULL));
        if (lane == 0)
            g_cbcol[f][d][jm] = ((unsigned long long)hi << 32) | lo;
    }
}

// ---------------- Gram via int8 tensor cores ----------------
// G[f] = X X^T, X = codebook transposed (D x M) as +-1 int8, generated from bits.
// grid = (F, 136) triangular 64x64 tiles, block 256 (8 warps).
// Warp tiling: 4 row groups of 16 x 2 col groups of 32 (nt = 4 subtiles of 8).
#define KC 256   // K chunk in m-elements (4 bit-words)
__global__ void __launch_bounds__(256) k_gram3() {
    __shared__ __align__(16) signed char sX[64][KC + 16];
    __shared__ __align__(16) signed char sY[64][KC + 16];
    __shared__ __half stage[64][72];
    __shared__ unsigned lut[16];

    int f = blockIdx.x;
    int p = blockIdx.y;                 // triangular pair index, 136 per f
    int tx = 0;
    while (p >= 16 - tx) { p -= 16 - tx; tx++; }
    int ty = tx + p;
    int x0 = tx * 64, y0 = ty * 64;

    int tid = threadIdx.x;
    int wid = tid >> 5, lane = tid & 31, g = lane >> 2, q = lane & 3;
    int mrow0 = (wid & 3) * 16;        // 4 row groups of 16
    int ncol0 = (wid >> 2) * 32;       // 2 col groups of 32

    if (tid < 16) {
        unsigned v = 0x01010101u;      // byte: bit ? 0xFF(-1) : 0x01(+1)
        if (tid & 1) v ^= 0x000000FEu;
        if (tid & 2) v ^= 0x0000FE00u;
        if (tid & 4) v ^= 0x00FE0000u;
        if (tid & 8) v ^= 0xFE000000u;
        lut[tid] = v;
    }
    __syncthreads();

    int acc[4][4];                     // [nt][c] ; warp tile 16 x 32 (4 n-subtiles of 8)
    #pragma unroll
    for (int i = 0; i < 4; i++)
        #pragma unroll
        for (int j = 0; j < 4; j++) acc[i][j] = 0;

    for (int kc = 0; kc < WPM; kc += 4) {      // 4 words = 256 m per chunk
        // convert bits -> int8 tiles: 2 tiles x 64 rows x 4 words = 512 words, 2/thread
        #pragma unroll
        for (int r = 0; r < 2; r++) {
            int idx = tid + 256 * r;           // 0..511
            int row = (idx >> 2) & 63, wj = idx & 3;
            unsigned long long w = (idx < 256) ? g_cbcol[f][x0 + row][kc + wj]
                                               : g_cbcol[f][y0 + row][kc + wj];
            unsigned* dst = (idx < 256) ? (unsigned*)&sX[row][wj * 64]
                                        : (unsigned*)&sY[row][wj * 64];
            #pragma unroll
            for (int nb = 0; nb < 16; nb++)
                dst[nb] = lut[(unsigned)(w >> (4 * nb)) & 15u];
        }
        __syncthreads();
        #pragma unroll
        for (int ks = 0; ks < KC; ks += 32) {
            unsigned a0 = *(const unsigned*)&sX[mrow0 + g    ][ks + q * 4];
            unsigned a1 = *(const unsigned*)&sX[mrow0 + 8 + g][ks + q * 4];
            unsigned a2 = *(const unsigned*)&sX[mrow0 + g    ][ks + 16 + q * 4];
            unsigned a3 = *(const unsigned*)&sX[mrow0 + 8 + g][ks + 16 + q * 4];
            #pragma unroll
            for (int nt = 0; nt < 4; nt++) {
                unsigned b0 = *(const unsigned*)&sY[ncol0 + nt * 8 + g][ks + q * 4];
                unsigned b1 = *(const unsigned*)&sY[ncol0 + nt * 8 + g][ks + 16 + q * 4];
                mma16832s8(acc[nt], a0, a1, a2, a3, b0, b1);
            }
        }
        __syncthreads();
    }

    // stage tile (rows = x, cols = y); values are exact even ints in [-4096,4096]
    #pragma unroll
    for (int nt = 0; nt < 4; nt++) {
        int r0 = mrow0 + g, c0 = ncol0 + nt * 8 + q * 2;
        stage[r0    ][c0    ] = __int2half_rn(acc[nt][0]);
        stage[r0    ][c0 + 1] = __int2half_rn(acc[nt][1]);
        stage[r0 + 8][c0    ] = __int2half_rn(acc[nt][2]);
        stage[r0 + 8][c0 + 1] = __int2half_rn(acc[nt][3]);
    }
    __syncthreads();

    // pass 1: G[x0+row][y0+col], coalesced
    #pragma unroll
    for (int r = 0; r < 2; r++) {
        int idx = tid + 256 * r;        // 512 uint4
        int row = idx >> 3, seg = idx & 7;
        *(uint4*)&g_G[f][x0 + row][y0 + seg * 8] = *(const uint4*)&stage[row][seg * 8];
    }

    // pass 2: transposed G[y0+r][x0+..] (skip for diagonal tiles)
    if (tx != ty) {
        int r = tid >> 2, qd = tid & 3;     // r: 0..63, qd: 0..3 (16-col quarters)
        unsigned wds[8];
        #pragma unroll
        for (int k = 0; k < 8; k++) {
            unsigned short h0 = __half_as_ushort(stage[qd * 16 + 2 * k    ][r]);
            unsigned short h1 = __half_as_ushort(stage[qd * 16 + 2 * k + 1][r]);
            wds[k] = ((unsigned)h1 << 16) | h0;
        }
        uint4 lo = make_uint4(wds[0], wds[1], wds[2], wds[3]);
        uint4 hi = make_uint4(wds[4], wds[5], wds[6], wds[7]);
        *(uint4*)&g_G[f][y0 + r][x0 + qd * 16    ] = lo;
        *(uint4*)&g_G[f][y0 + r][x0 + qd * 16 + 8] = hi;
    }
}

// ---------------- fused iteration kernel ----------------
// upd = sign(new_est @ G[f]), pack to bits, diff flag, double-buffered est.
// grid = (F, 16, 2), block = 256 (8 warps). Block tile: 32(B) x 64(d), K = D.
__global__ void __launch_bounds__(256) k_iter(int t) {
    const int rbuf = t & 1, wbuf = (t & 1) ^ 1;
    __shared__ unsigned long long snew[32][WPD + 1];   // new_est bits, this f / b-half
    __shared__ __align__(16) __half shB[64][72];       // G chunk [d][k]
    __shared__ unsigned char sbytes[32][64];           // sign bytes

    int f  = blockIdx.x;
    int jd = blockIdx.y;               // d-tile (64 d per word)
    int b0 = blockIdx.z * 32;          // batch half
    int tid = threadIdx.x;
    int wid = tid >> 5, lane = tid & 31, g = lane >> 2, q = lane & 3;
    int mrow0 = (wid >> 2) * 16;       // 2 row groups of 16
    int ncol0 = (wid & 3) * 16;        // 4 col groups of 16

    // new_est bits: in ^ (xor over all f) ^ est_f, 512 words
    #pragma unroll
    for (int r = 0; r < 2; r++) {
        int idx = tid + 256 * r;
        int bl = idx >> 4, j = idx & 15;
        int b = b0 + bl;
        unsigned long long tot = g_in_bits[b][j];
        #pragma unroll
        for (int ff = 0; ff < F; ff++) tot ^= g_est[rbuf][b][ff][j];
        snew[bl][j] = tot ^ g_est[rbuf][b][f][j];
    }
    __syncthreads();

    float acc[2][4];
    #pragma unroll
    for (int i = 0; i < 2; i++)
        #pragma unroll
        for (int jj = 0; jj < 4; jj++) acc[i][jj] = 0.f;

    const int d0 = jd * 64;
    for (int kc = 0; kc < D; kc += 64) {
        // load G chunk: 64 rows (d) x 64 halves (k) = 512 uint4, 2 per thread
        #pragma unroll
        for (int r = 0; r < 2; r++) {
            int idx = tid + 256 * r;
            int row = idx >> 3, seg = idx & 7;
            *(uint4*)&shB[row][seg * 8] =
                *(const uint4*)&g_G[f][d0 + row][kc + seg * 8];
        }
        __syncthreads();
        unsigned long long w0 = snew[mrow0 + g][kc >> 6];
        unsigned long long w1 = snew[mrow0 + 8 + g][kc >> 6];
        #pragma unroll
        for (int kk = 0; kk < 64; kk += 16) {
            unsigned a0 = bits2h2((unsigned)(w0 >> (kk + q * 2)) & 3u);
            unsigned a1 = bits2h2((unsigned)(w1 >> (kk + q * 2)) & 3u);
            unsigned a2 = bits2h2((unsigned)(w0 >> (kk + 8 + q * 2)) & 3u);
            unsigned a3 = bits2h2((unsigned)(w1 >> (kk + 8 + q * 2)) & 3u);
            #pragma unroll
            for (int nt = 0; nt < 2; nt++) {
                unsigned b0v = *(const unsigned*)&shB[ncol0 + nt * 8 + g][kk + q * 2];
                unsigned b1v = *(const unsigned*)&shB[ncol0 + nt * 8 + g][kk + 8 + q * 2];
                mma16816(acc[nt], a0, a1, a2, a3, b0v, b1v);
            }
        }
        __syncthreads();
    }

    // epilogue: sign bytes -> smem
    int r0 = mrow0 + g;
    #pragma unroll
    for (int nt = 0; nt < 2; nt++) {
        int c0 = ncol0 + nt * 8 + q * 2;
        sbytes[r0    ][c0    ] = (unsigned char)(acc[nt][0] < 0.f);
        sbytes[r0    ][c0 + 1] = (unsigned char)(acc[nt][1] < 0.f);
        sbytes[r0 + 8][c0    ] = (unsigned char)(acc[nt][2] < 0.f);
        sbytes[r0 + 8][c0 + 1] = (unsigned char)(acc[nt][3] < 0.f);
    }
    __syncthreads();

    if (tid < 32) {
        const unsigned long long* q8 = (const unsigned long long*)sbytes[tid];
        unsigned long long w = 0ULL;
        #pragma unroll
        for (int s = 0; s < 8; s++) {
            unsigned long long x = q8[s];
            #pragma unroll
            for (int k = 0; k < 8; k++)
                w |= ((x >> (8 * k)) & 1ULL) << (8 * s + k);
        }
        int b = b0 + tid;
        bool diff = (w != g_est[rbuf][b][f][jd]);
        g_est[wbuf][b][f][jd] = w;
        unsigned bal = __ballot_sync(0xffffffffu, diff);
        if (lane == 0 && bal) atomicOr(&g_diff[t], 1);
    }
}

// ---------------- cleanup: partial argmax over m-chunks via atomicMax ----------------
// grid = (F, M/256, B/8), block = 256
__global__ void k_cleanup() {
    int f = blockIdx.x;
    int m = blockIdx.y * 256 + threadIdx.x;
    int b0 = blockIdx.z * 8;
    __shared__ unsigned long long sh[8][WPD];
    __shared__ int skey[8][33];
    if (threadIdx.x < 128) {
        int bb = threadIdx.x >> 4, j = threadIdx.x & 15;
        sh[bb][j] = g_est[FINAL_BUF][b0 + bb][f][j];
    }
    __syncthreads();
    int acc[8];
    #pragma unroll
    for (int i = 0; i < 8; i++) acc[i] = 0;
    #pragma unroll
    for (int j = 0; j < WPD; j++) {
        unsigned long long w = g_cb_bits[f][j][m];
        #pragma unroll
        for (int bb = 0; bb < 8; bb++) acc[bb] += __popcll(w ^ sh[bb][j]);
    }
    int lane = threadIdx.x & 31, wid = threadIdx.x >> 5;
    #pragma unroll
    for (int bb = 0; bb < 8; bb++) {
        int vv = D - 2 * acc[bb];
        int a = vv < 0 ? -vv : vv;
        int key = (a << 12) | (4095 - m);
        #pragma unroll
        for (int s = 16; s > 0; s >>= 1) {
            int o = __shfl_down_sync(0xffffffffu, key, s);
            if (o > key) key = o;
        }
        if (lane == 0) skey[bb][wid] = key;
    }
    __syncthreads();
    if (threadIdx.x < 8) {
        int bb = threadIdx.x;
        int best = skey[bb][0];
        #pragma unroll
        for (int w2 = 1; w2 < 8; w2++)
            if (skey[bb][w2] > best) best = skey[bb][w2];
        atomicMax(&g_key[(b0 + bb) * F + f], best);
    }
}

// ---------------- combined output kernel ----------------
__global__ void k_out(float* __restrict__ out_outcome,
                      float* __restrict__ out_est,
                      float* __restrict__ out_misc) {
    int idx = blockIdx.x * 256 + threadIdx.x;   // est: b*F*D + f*D + d
    if (out_est) {
        int d = idx & (D - 1);
        int f = (idx >> 10) & 3;
        int b = idx >> 12;
        unsigned long long w = g_est[FINAL_BUF][b][f][d >> 6];
        out_est[idx] = ((w >> (d & 63)) & 1ULL) ? -1.f : 1.f;
    }
    if (blockIdx.x == 0) {
        if (out_outcome && threadIdx.x < B * F)
            out_outcome[threadIdx.x] = (float)(4095 - (g_key[threadIdx.x] & 4095));
        if (out_misc && threadIdx.x == 0) {
            int iters = ITERS, conv = 0;
            for (int t = 0; t < ITERS; t++) {
                if (g_diff[t] == 0) { iters = t + 1; conv = 1; break; }
            }
            out_misc[0] = (float)iters;
            out_misc[1] = (float)conv;
        }
    }
}

// ---------------- launcher ----------------
extern "C" void kernel_launch(void* const* d_in, const int* in_sizes, int n_in,
                              void* d_out, int out_size) {
    const float* input = nullptr;
    const float* est0  = nullptr;
    const float* cb    = nullptr;
    for (int i = 0; i < n_in; i++) {
        if      (in_sizes[i] == B * D)     input = (const float*)d_in[i];
        else if (in_sizes[i] == B * F * D) est0  = (const float*)d_in[i];
        else if (in_sizes[i] == F * M * D) cb    = (const float*)d_in[i];
    }
    if (!input) input = (const float*)d_in[0];
    if (!est0)  est0  = (const float*)d_in[1];
    if (!cb)    cb    = (const float*)d_in[2];
    float* out = (float*)d_out;

    const int n_small = B * WPD + B * F * WPD + ITERS + B * F;
    k_pack_small<<<(n_small + 255) / 256, 256>>>(input, est0);
    k_pack_cb<<<F * WPD * M / 256, 256>>>(cb);
    k_transpose_bits<<<dim3(F, M / 64), 256>>>();
    k_gram3<<<dim3(F, 136), 256>>>();

    for (int t = 0; t < ITERS; t++) {
        k_iter<<<dim3(F, D / 64, 2), 256>>>(t);
    }

    k_cleanup<<<dim3(F, M / 256, B / 8), 256>>>();

    // output layout (float32): order (outcome, est, iters, conv)
    const long long n_out = B * F;                 // 256
    const long long n_est = (long long)B * F * D;  // 262144
    long long off_outcome = -1, off_est = -1, off_misc = -1;
    if ((long long)out_size >= n_out + n_est + 2) {
        off_outcome = 0; off_est = n_out; off_misc = n_out + n_est;
    } else if ((long long)out_size == n_est) {
        off_est = 0;
    } else if ((long long)out_size == n_out) {
        off_outcome = 0;
    } else if ((long long)out_size == n_out + n_est) {
        off_outcome = 0; off_est = n_out;
    } else {
        off_outcome = 0;
    }

    k_out<<<(B * F * D) / 256, 256>>>(
        off_outcome >= 0 ? out + off_outcome : nullptr,
        off_est     >= 0 ? out + off_est     : nullptr,
        off_misc    >= 0 ? out + off_misc    : nullptr);
}

// round 9
// speedup vs baseline: 1.2107x; 1.2107x over previous
#include <cuda_runtime.h>
#include <cuda_fp16.h>
#include <cstdint>

#define B 64
#define F 4
#define M 4096
#define D 1024
#define ITERS 15
#define WPD 16   // 64-bit words per D-dim vector
#define WPM 64   // 64-bit words per M-dim vector
#define FINAL_BUF (ITERS & 1)
#define NBLK 128 // persistent kernel blocks (must all be co-resident; 128 < 148 SMs)

// ---------------- device scratch (no allocs allowed) ----------------
__device__ unsigned long long g_cb_bits[F][WPD][M];   // codebook bits over d, [f][word][m] (2 MB)
__device__ unsigned long long g_cbcol[F][D][WPM];     // codebook bits over m, [f][d][word] (2 MB)
__device__ __half             g_G[F][D][D];           // Gram matrix C^T C, exact even ints (8 MB)
__device__ unsigned long long g_in_bits[B][WPD];
__device__ unsigned long long g_est[2][B][F][WPD];    // double-buffered estimates (bit 1 = -1)
__device__ int                g_key[B * F];           // argmax keys (atomicMax)
__device__ int                g_diff[ITERS];          // per-iteration "changed" flags
__device__ unsigned           g_bar_count;            // grid barrier state
__device__ unsigned           g_bar_gen;

// ---------------- helpers ----------------
__device__ __forceinline__ unsigned long long pack64(const float* p) {
    unsigned long long w = 0ULL;
    #pragma unroll
    for (int t = 0; t < 16; t++) {
        float4 v = reinterpret_cast<const float4*>(p)[t];
        w |= ((unsigned long long)(v.x < 0.f)) << (4 * t + 0);
        w |= ((unsigned long long)(v.y < 0.f)) << (4 * t + 1);
        w |= ((unsigned long long)(v.z < 0.f)) << (4 * t + 2);
        w |= ((unsigned long long)(v.w < 0.f)) << (4 * t + 3);
    }
    return w;
}

__device__ __forceinline__ void mma16816(float* c,
                                         unsigned a0, unsigned a1, unsigned a2, unsigned a3,
                                         unsigned b0, unsigned b1) {
    asm volatile(
        "mma.sync.aligned.m16n8k16.row.col.f32.f16.f16.f32 "
        "{%0,%1,%2,%3}, {%4,%5,%6,%7}, {%8,%9}, {%0,%1,%2,%3};"
        : "+f"(c[0]), "+f"(c[1]), "+f"(c[2]), "+f"(c[3])
        : "r"(a0), "r"(a1), "r"(a2), "r"(a3), "r"(b0), "r"(b1));
}

// bits (2 low bits, 1 = negative) -> packed half2 {+-1, +-1}
__device__ __forceinline__ unsigned bits2h2(unsigned bits) {
    return 0x3C003C00u ^ ((bits & 1u) << 15) ^ ((bits & 2u) << 30);
}

// all-atomic grid barrier (deterministic; all NBLK blocks co-resident)
__device__ __forceinline__ void grid_barrier() {
    __syncthreads();
    if (threadIdx.x == 0) {
        __threadfence();
        unsigned gen = atomicAdd(&g_bar_gen, 0u);
        if (atomicAdd(&g_bar_count, 1u) == NBLK - 1) {
            atomicExch(&g_bar_count, 0u);
            atomicAdd(&g_bar_gen, 1u);
        } else {
            while (atomicAdd(&g_bar_gen, 0u) == gen) {}
        }
        __threadfence();
    }
    __syncthreads();
}

// ---------------- packing kernels ----------------
__global__ void k_pack_small(const float* __restrict__ input,
                             const float* __restrict__ est0) {
    int idx = blockIdx.x * 256 + threadIdx.x;
    const int base = B * WPD + B * F * WPD;
    if (idx < B * WPD) {
        int b = idx >> 4, j = idx & 15;
        g_in_bits[b][j] = pack64(input + b * D + j * 64);
    } else if (idx < base) {
        int w = idx - B * WPD;
        int b = w >> 6, f = (w >> 4) & 3, j = w & 15;
        g_est[0][b][f][j] = pack64(est0 + (size_t)(b * F + f) * D + j * 64);
    } else if (idx < base + ITERS) {
        g_diff[idx - base] = 0;
    } else if (idx < base + ITERS + B * F) {
        g_key[idx - base - ITERS] = -1;
    } else if (idx == base + ITERS + B * F) {
        g_bar_count = 0u;
        g_bar_gen = 0u;
    }
}

__global__ void k_pack_cb(const float* __restrict__ cb) {
    int idx = blockIdx.x * 256 + threadIdx.x;   // F*WPD*M total
    int m = idx & (M - 1);
    int j = (idx >> 12) & 15;
    int f = idx >> 16;
    g_cb_bits[f][j][m] = pack64(cb + ((size_t)(f * M + m)) * D + j * 64);
}

// ---------------- bit transpose: g_cb_bits (d-words over m) -> g_cbcol (m-words over d) ----
// grid = (F, M/64), block = 256 (8 warps).
__global__ void __launch_bounds__(256) k_transpose_bits() {
    __shared__ unsigned long long sm[64][17];   // [m_local][jd]
    int f  = blockIdx.x;
    int jm = blockIdx.y;       // which m-word (64 m's)
    int tid = threadIdx.x;
    #pragma unroll
    for (int r = 0; r < 4; r++) {
        int idx = tid + 256 * r;       // 1024 words
        int m = idx & 63, j = idx >> 6;
        sm[m][j] = g_cb_bits[f][j][jm * 64 + m];
    }
    __syncthreads();
    int wid = tid >> 5, lane = tid & 31;
    for (int i = 0; i < 128; i++) {
        int d = wid * 128 + i;
        int j = d >> 6, bp = d & 63;
        unsigned lo = __ballot_sync(0xffffffffu,
            (unsigned)((sm[lane][j] >> bp) & 1ULL));
        unsigned hi = __ballot_sync(0xffffffffu,
            (unsigned)((sm[lane + 32][j] >> bp) & 1ULL));
        if (lane == 0)
            g_cbcol[f][d][jm] = ((unsigned long long)hi << 32) | lo;
    }
}

// ---------------- Gram: symmetric, 64x64 tiles, 4x4 per thread (popcount) ----------------
__global__ void __launch_bounds__(256) k_gram2() {
    __shared__ unsigned long long shX[64][19];   // padded: conflict-free strided reads
    __shared__ unsigned long long shY[64][19];
    __shared__ __half stage[64][72];

    int f = blockIdx.x;
    int p = blockIdx.y;                 // triangular pair index, 136 per f
    int tx = 0;
    while (p >= 16 - tx) { p -= 16 - tx; tx++; }
    int ty = tx + p;
    int x0 = tx * 64, y0 = ty * 64;

    int tid = threadIdx.x;
    int u = (tid >> 4) * 4;             // x sub-row (0..60)
    int v = (tid & 15) * 4;             // y sub-row (0..60)

    int acc[4][4];
    #pragma unroll
    for (int i = 0; i < 4; i++)
        #pragma unroll
        for (int j = 0; j < 4; j++) acc[i][j] = 0;

    for (int kc = 0; kc < WPM; kc += 16) {
        #pragma unroll
        for (int r = 0; r < 4; r++) {
            int idx = tid + 256 * r;    // 1024 words
            int row = idx >> 4, w = idx & 15;
            shX[row][w] = g_cbcol[f][x0 + row][kc + w];
            shY[row][w] = g_cbcol[f][y0 + row][kc + w];
        }
        __syncthreads();
        #pragma unroll
        for (int w = 0; w < 16; w++) {
            unsigned long long x0v = shX[u    ][w];
            unsigned long long x1v = shX[u + 1][w];
            unsigned long long x2v = shX[u + 2][w];
            unsigned long long x3v = shX[u + 3][w];
            unsigned long long y0v = shY[v    ][w];
            unsigned long long y1v = shY[v + 1][w];
            unsigned long long y2v = shY[v + 2][w];
            unsigned long long y3v = shY[v + 3][w];
            acc[0][0] += __popcll(x0v ^ y0v); acc[0][1] += __popcll(x0v ^ y1v);
            acc[0][2] += __popcll(x0v ^ y2v); acc[0][3] += __popcll(x0v ^ y3v);
            acc[1][0] += __popcll(x1v ^ y0v); acc[1][1] += __popcll(x1v ^ y1v);
            acc[1][2] += __popcll(x1v ^ y2v); acc[1][3] += __popcll(x1v ^ y3v);
            acc[2][0] += __popcll(x2v ^ y0v); acc[2][1] += __popcll(x2v ^ y1v);
            acc[2][2] += __popcll(x2v ^ y2v); acc[2][3] += __popcll(x2v ^ y3v);
            acc[3][0] += __popcll(x3v ^ y0v); acc[3][1] += __popcll(x3v ^ y1v);
            acc[3][2] += __popcll(x3v ^ y2v); acc[3][3] += __popcll(x3v ^ y3v);
        }
        __syncthreads();
    }

    // stage tile (rows = x, cols = y)
    #pragma unroll
    for (int i = 0; i < 4; i++)
        #pragma unroll
        for (int j = 0; j < 4; j++)
            stage[u + i][v + j] = __int2half_rn(M - 2 * acc[i][j]);
    __syncthreads();

    // pass 1: G[x0+row][y0+col], coalesced
    #pragma unroll
    for (int r = 0; r < 2; r++) {
        int idx = tid + 256 * r;        // 512 uint4
        int row = idx >> 3, seg = idx & 7;
        *(uint4*)&g_G[f][x0 + row][y0 + seg * 8] = *(const uint4*)&stage[row][seg * 8];
    }

    // pass 2: transposed G[y0+r][x0+..] (skip for diagonal tiles)
    if (tx != ty) {
        int r = tid >> 2, qd = tid & 3;     // r: 0..63, qd: 0..3 (16-col quarters)
        unsigned wds[8];
        #pragma unroll
        for (int k = 0; k < 8; k++) {
            unsigned short h0 = __half_as_ushort(stage[qd * 16 + 2 * k    ][r]);
            unsigned short h1 = __half_as_ushort(stage[qd * 16 + 2 * k + 1][r]);
            wds[k] = ((unsigned)h1 << 16) | h0;
        }
        uint4 lo = make_uint4(wds[0], wds[1], wds[2], wds[3]);
        uint4 hi = make_uint4(wds[4], wds[5], wds[6], wds[7]);
        *(uint4*)&g_G[f][y0 + r][x0 + qd * 16    ] = lo;
        *(uint4*)&g_G[f][y0 + r][x0 + qd * 16 + 8] = hi;
    }
}

// ---------------- persistent mega kernel: 15 iterations + cleanup + outputs ----------------
// grid = (F, 16, 2) = 128 blocks, block = 256 (8 warps).
__global__ void __launch_bounds__(256) k_mega(float* __restrict__ out_outcome,
                                              float* __restrict__ out_est,
                                              float* __restrict__ out_misc) {
    __shared__ unsigned long long snew[32][WPD + 1];   // new_est bits, this f / b-half
    __shared__ __align__(16) __half shB[64][72];       // G chunk [d][k]
    __shared__ unsigned char sbytes[32][64];           // sign bytes
    __shared__ unsigned long long sest[64][WPD];       // cleanup: final est, this f

    const int f  = blockIdx.x;
    const int jd = blockIdx.y;               // d-tile (64 d per word)
    const int b0 = blockIdx.z * 32;          // batch half
    const int tid = threadIdx.x;
    const int wid = tid >> 5, lane = tid & 31, g = lane >> 2, q = lane & 3;
    const int mrow0 = (wid >> 2) * 16;       // 2 row groups of 16
    const int ncol0 = (wid & 3) * 16;        // 4 col groups of 16
    const int d0 = jd * 64;

    for (int t = 0; t < ITERS; t++) {
        const int rbuf = t & 1, wbuf = (t & 1) ^ 1;

        // new_est bits: in ^ (xor over all f) ^ est_f, 512 words
        #pragma unroll
        for (int r = 0; r < 2; r++) {
            int idx = tid + 256 * r;
            int bl = idx >> 4, j = idx & 15;
            int b = b0 + bl;
            unsigned long long tot = g_in_bits[b][j];
            #pragma unroll
            for (int ff = 0; ff < F; ff++) tot ^= g_est[rbuf][b][ff][j];
            snew[bl][j] = tot ^ g_est[rbuf][b][f][j];
        }
        __syncthreads();

        float acc[2][4];
        #pragma unroll
        for (int i = 0; i < 2; i++)
            #pragma unroll
            for (int jj = 0; jj < 4; jj++) acc[i][jj] = 0.f;

        for (int kc = 0; kc < D; kc += 64) {
            #pragma unroll
            for (int r = 0; r < 2; r++) {
                int idx = tid + 256 * r;
                int row = idx >> 3, seg = idx & 7;
                *(uint4*)&shB[row][seg * 8] =
                    *(const uint4*)&g_G[f][d0 + row][kc + seg * 8];
            }
            __syncthreads();
            unsigned long long w0 = snew[mrow0 + g][kc >> 6];
            unsigned long long w1 = snew[mrow0 + 8 + g][kc >> 6];
            #pragma unroll
            for (int kk = 0; kk < 64; kk += 16) {
                unsigned a0 = bits2h2((unsigned)(w0 >> (kk + q * 2)) & 3u);
                unsigned a1 = bits2h2((unsigned)(w1 >> (kk + q * 2)) & 3u);
                unsigned a2 = bits2h2((unsigned)(w0 >> (kk + 8 + q * 2)) & 3u);
                unsigned a3 = bits2h2((unsigned)(w1 >> (kk + 8 + q * 2)) & 3u);
                #pragma unroll
                for (int nt = 0; nt < 2; nt++) {
                    unsigned b0v = *(const unsigned*)&shB[ncol0 + nt * 8 + g][kk + q * 2];
                    unsigned b1v = *(const unsigned*)&shB[ncol0 + nt * 8 + g][kk + 8 + q * 2];
                    mma16816(acc[nt], a0, a1, a2, a3, b0v, b1v);
                }
            }
            __syncthreads();
        }

        // epilogue: sign bytes -> smem
        int r0 = mrow0 + g;
        #pragma unroll
        for (int nt = 0; nt < 2; nt++) {
            int c0 = ncol0 + nt * 8 + q * 2;
            sbytes[r0    ][c0    ] = (unsigned char)(acc[nt][0] < 0.f);
            sbytes[r0    ][c0 + 1] = (unsigned char)(acc[nt][1] < 0.f);
            sbytes[r0 + 8][c0    ] = (unsigned char)(acc[nt][2] < 0.f);
            sbytes[r0 + 8][c0 + 1] = (unsigned char)(acc[nt][3] < 0.f);
        }
        __syncthreads();

        if (tid < 32) {
            const unsigned long long* q8 = (const unsigned long long*)sbytes[tid];
            unsigned long long w = 0ULL;
            #pragma unroll
            for (int s = 0; s < 8; s++) {
                unsigned long long x = q8[s];
                #pragma unroll
                for (int k = 0; k < 8; k++)
                    w |= ((x >> (8 * k)) & 1ULL) << (8 * s + k);
            }
            int b = b0 + tid;
            bool diff = (w != g_est[rbuf][b][f][jd]);
            g_est[wbuf][b][f][jd] = w;
            unsigned bal = __ballot_sync(0xffffffffu, diff);
            if (lane == 0 && bal) atomicOr(&g_diff[t], 1);
        }
        grid_barrier();
    }

    // ---- cleanup: partial argmax over this block's m-chunk (128 m), all 64 b ----
    {
        #pragma unroll
        for (int r = 0; r < 4; r++) {
            int idx = tid + 256 * r;          // 1024 words
            int b = idx >> 4, j = idx & 15;
            sest[b][j] = g_est[FINAL_BUF][b][f][j];
        }
        __syncthreads();

        int m = (jd * 2 + blockIdx.z) * 128 + (tid & 127);
        int bh = (tid >> 7) * 32;             // b half: 0 or 32
        for (int bb = 0; bb < 32; bb++) {
            int b = bh + bb;
            int acc = 0;
            #pragma unroll
            for (int j = 0; j < WPD; j++)
                acc += __popcll(g_cb_bits[f][j][m] ^ sest[b][j]);
            int vv = D - 2 * acc;
            int a = vv < 0 ? -vv : vv;
            int key = (a << 12) | (4095 - m);
            #pragma unroll
            for (int s = 16; s > 0; s >>= 1) {
                int o = __shfl_down_sync(0xffffffffu, key, s);
                if (o > key) key = o;
            }
            if (lane == 0) atomicMax(&g_key[b * F + f], key);
        }
    }

    // ---- est output: 2048 floats per block ----
    if (out_est) {
        int blk = (f * 16 + jd) * 2 + blockIdx.z;
        int base = blk * 2048;
        #pragma unroll
        for (int r = 0; r < 8; r++) {
            int idx = base + tid + 256 * r;    // b*F*D + f*D + d
            int d = idx & (D - 1);
            int ff = (idx >> 10) & 3;
            int b = idx >> 12;
            unsigned long long w = g_est[FINAL_BUF][b][ff][d >> 6];
            out_est[idx] = ((w >> (d & 63)) & 1ULL) ? -1.f : 1.f;
        }
    }

    grid_barrier();

    // ---- outcome + misc (block 0 only, after all atomicMax done) ----
    if (f == 0 && jd == 0 && blockIdx.z == 0) {
        if (out_outcome && tid < B * F)
            out_outcome[tid] = (float)(4095 - (g_key[tid] & 4095));
        if (out_misc && tid == 0) {
            int iters = ITERS, conv = 0;
            for (int t = 0; t < ITERS; t++) {
                if (g_diff[t] == 0) { iters = t + 1; conv = 1; break; }
            }
            out_misc[0] = (float)iters;
            out_misc[1] = (float)conv;
        }
    }
}

// ---------------- launcher ----------------
extern "C" void kernel_launch(void* const* d_in, const int* in_sizes, int n_in,
                              void* d_out, int out_size) {
    const float* input = nullptr;
    const float* est0  = nullptr;
    const float* cb    = nullptr;
    for (int i = 0; i < n_in; i++) {
        if      (in_sizes[i] == B * D)     input = (const float*)d_in[i];
        else if (in_sizes[i] == B * F * D) est0  = (const float*)d_in[i];
        else if (in_sizes[i] == F * M * D) cb    = (const float*)d_in[i];
    }
    if (!input) input = (const float*)d_in[0];
    if (!est0)  est0  = (const float*)d_in[1];
    if (!cb)    cb    = (const float*)d_in[2];
    float* out = (float*)d_out;

    const int n_small = B * WPD + B * F * WPD + ITERS + B * F + 1;
    k_pack_small<<<(n_small + 255) / 256, 256>>>(input, est0);
    k_pack_cb<<<F * WPD * M / 256, 256>>>(cb);
    k_transpose_bits<<<dim3(F, M / 64), 256>>>();
    k_gram2<<<dim3(F, 136), 256>>>();

    // output layout (float32): order (outcome, est, iters, conv)
    const long long n_out = B * F;                 // 256
    const long long n_est = (long long)B * F * D;  // 262144
    long long off_outcome = -1, off_est = -1, off_misc = -1;
    if ((long long)out_size >= n_out + n_est + 2) {
        off_outcome = 0; off_est = n_out; off_misc = n_out + n_est;
    } else if ((long long)out_size == n_est) {
        off_est = 0;
    } else if ((long long)out_size == n_out) {
        off_outcome = 0;
    } else if ((long long)out_size == n_out + n_est) {
        off_outcome = 0; off_est = n_out;
    } else {
        off_outcome = 0;
    }

    k_mega<<<dim3(F, 16, 2), 256>>>(
        off_outcome >= 0 ? out + off_outcome : nullptr,
        off_est     >= 0 ? out + off_est     : nullptr,
        off_misc    >= 0 ? out + off_misc    : nullptr);
}

// round 10
// speedup vs baseline: 1.3249x; 1.0943x over previous
#include <cuda_runtime.h>
#include <cuda_fp16.h>
#include <cstdint>

#define B 64
#define F 4
#define M 4096
#define D 1024
#define ITERS 15
#define WPD 16   // 64-bit words per D-dim vector
#define WPM 64   // 64-bit words per M-dim vector
#define FINAL_BUF (ITERS & 1)

// ---------------- device scratch (no allocs allowed) ----------------
__device__ unsigned long long g_cb_bits[F][WPD][M];   // codebook bits over d, [f][word][m] (2 MB)
__device__ unsigned long long g_cbcol[F][D][WPM];     // codebook bits over m, [f][d][word] (2 MB)
__device__ __half             g_G[F][D][D];           // Gram matrix C^T C, exact even ints (8 MB)
__device__ unsigned long long g_in_bits[B][WPD];
__device__ unsigned long long g_est[2][B][F][WPD];    // double-buffered estimates (bit 1 = -1)
__device__ int                g_key[B * F];           // argmax keys (atomicMax)
__device__ int                g_diff[ITERS];          // per-iteration "changed" flags

// ---------------- helpers ----------------
__device__ __forceinline__ unsigned long long pack64(const float* p) {
    unsigned long long w = 0ULL;
    #pragma unroll
    for (int t = 0; t < 16; t++) {
        float4 v = reinterpret_cast<const float4*>(p)[t];
        w |= ((unsigned long long)(v.x < 0.f)) << (4 * t + 0);
        w |= ((unsigned long long)(v.y < 0.f)) << (4 * t + 1);
        w |= ((unsigned long long)(v.z < 0.f)) << (4 * t + 2);
        w |= ((unsigned long long)(v.w < 0.f)) << (4 * t + 3);
    }
    return w;
}

__device__ __forceinline__ void mma16816(float* c,
                                         unsigned a0, unsigned a1, unsigned a2, unsigned a3,
                                         unsigned b0, unsigned b1) {
    asm volatile(
        "mma.sync.aligned.m16n8k16.row.col.f32.f16.f16.f32 "
        "{%0,%1,%2,%3}, {%4,%5,%6,%7}, {%8,%9}, {%0,%1,%2,%3};"
        : "+f"(c[0]), "+f"(c[1]), "+f"(c[2]), "+f"(c[3])
        : "r"(a0), "r"(a1), "r"(a2), "r"(a3), "r"(b0), "r"(b1));
}

// bits (2 low bits, 1 = negative) -> packed half2 {+-1, +-1}
__device__ __forceinline__ unsigned bits2h2(unsigned bits) {
    return 0x3C003C00u ^ ((bits & 1u) << 15) ^ ((bits & 2u) << 30);
}

// ---------------- packing kernels ----------------
__global__ void k_pack_small(const float* __restrict__ input,
                             const float* __restrict__ est0) {
    int idx = blockIdx.x * 256 + threadIdx.x;
    const int base = B * WPD + B * F * WPD;
    if (idx < B * WPD) {
        int b = idx >> 4, j = idx & 15;
        g_in_bits[b][j] = pack64(input + b * D + j * 64);
    } else if (idx < base) {
        int w = idx - B * WPD;
        int b = w >> 6, f = (w >> 4) & 3, j = w & 15;
        g_est[0][b][f][j] = pack64(est0 + (size_t)(b * F + f) * D + j * 64);
    } else if (idx < base + ITERS) {
        g_diff[idx - base] = 0;
    } else if (idx < base + ITERS + B * F) {
        g_key[idx - base - ITERS] = -1;
    }
}

// coalesced ballot-based codebook packing: warp per m-row
// grid = (F, M/8), block = 256 (8 warps)
__global__ void __launch_bounds__(256) k_pack_cb2(const float* __restrict__ cb) {
    int f = blockIdx.x;
    int m = blockIdx.y * 8 + (threadIdx.x >> 5);
    int lane = threadIdx.x & 31;
    const float* row = cb + ((size_t)(f * M + m)) * D;
    #pragma unroll
    for (int j = 0; j < WPD; j++) {
        unsigned lo = __ballot_sync(0xffffffffu, row[j * 64 + lane] < 0.f);
        unsigned hi = __ballot_sync(0xffffffffu, row[j * 64 + 32 + lane] < 0.f);
        if (lane == 0)
            g_cb_bits[f][j][m] = ((unsigned long long)hi << 32) | lo;
    }
}

// ---------------- bit transpose: g_cb_bits (d-words over m) -> g_cbcol (m-words over d) ----
// grid = (F, M/64), block = 256 (8 warps).
__global__ void __launch_bounds__(256) k_transpose_bits() {
    __shared__ unsigned long long sm[64][17];   // [m_local][jd]
    int f  = blockIdx.x;
    int jm = blockIdx.y;       // which m-word (64 m's)
    int tid = threadIdx.x;
    #pragma unroll
    for (int r = 0; r < 4; r++) {
        int idx = tid + 256 * r;       // 1024 words
        int m = idx & 63, j = idx >> 6;
        sm[m][j] = g_cb_bits[f][j][jm * 64 + m];
    }
    __syncthreads();
    int wid = tid >> 5, lane = tid & 31;
    for (int i = 0; i < 128; i++) {
        int d = wid * 128 + i;
        int j = d >> 6, bp = d & 63;
        unsigned lo = __ballot_sync(0xffffffffu,
            (unsigned)((sm[lane][j] >> bp) & 1ULL));
        unsigned hi = __ballot_sync(0xffffffffu,
            (unsigned)((sm[lane + 32][j] >> bp) & 1ULL));
        if (lane == 0)
            g_cbcol[f][d][jm] = ((unsigned long long)hi << 32) | lo;
    }
}

// ---------------- Gram: symmetric, 64x64 tiles, 4x4 per thread (popcount) ----------------
// grid = (F, 68), each block does tiles p and p+68 (136 triangular tiles per f).
__global__ void __launch_bounds__(256) k_gram2() {
    __shared__ unsigned long long shX[64][19];   // padded: conflict-free strided reads
    __shared__ unsigned long long shY[64][19];
    __shared__ __half stage[64][72];

    int f = blockIdx.x;
    int tid = threadIdx.x;
    int u = (tid >> 4) * 4;             // x sub-row (0..60)
    int v = (tid & 15) * 4;             // y sub-row (0..60)

    for (int half = 0; half < 2; half++) {
        int p = blockIdx.y + half * 68;     // triangular pair index, 136 per f
        int tx = 0;
        while (p >= 16 - tx) { p -= 16 - tx; tx++; }
        int ty = tx + p;
        int x0 = tx * 64, y0 = ty * 64;

        int acc[4][4];
        #pragma unroll
        for (int i = 0; i < 4; i++)
            #pragma unroll
            for (int j = 0; j < 4; j++) acc[i][j] = 0;

        for (int kc = 0; kc < WPM; kc += 16) {
            #pragma unroll
            for (int r = 0; r < 4; r++) {
                int idx = tid + 256 * r;    // 1024 words
                int row = idx >> 4, w = idx & 15;
                shX[row][w] = g_cbcol[f][x0 + row][kc + w];
                shY[row][w] = g_cbcol[f][y0 + row][kc + w];
            }
            __syncthreads();
            #pragma unroll
            for (int w = 0; w < 16; w++) {
                unsigned long long x0v = shX[u    ][w];
                unsigned long long x1v = shX[u + 1][w];
                unsigned long long x2v = shX[u + 2][w];
                unsigned long long x3v = shX[u + 3][w];
                unsigned long long y0v = shY[v    ][w];
                unsigned long long y1v = shY[v + 1][w];
                unsigned long long y2v = shY[v + 2][w];
                unsigned long long y3v = shY[v + 3][w];
                acc[0][0] += __popcll(x0v ^ y0v); acc[0][1] += __popcll(x0v ^ y1v);
                acc[0][2] += __popcll(x0v ^ y2v); acc[0][3] += __popcll(x0v ^ y3v);
                acc[1][0] += __popcll(x1v ^ y0v); acc[1][1] += __popcll(x1v ^ y1v);
                acc[1][2] += __popcll(x1v ^ y2v); acc[1][3] += __popcll(x1v ^ y3v);
                acc[2][0] += __popcll(x2v ^ y0v); acc[2][1] += __popcll(x2v ^ y1v);
                acc[2][2] += __popcll(x2v ^ y2v); acc[2][3] += __popcll(x2v ^ y3v);
                acc[3][0] += __popcll(x3v ^ y0v); acc[3][1] += __popcll(x3v ^ y1v);
                acc[3][2] += __popcll(x3v ^ y2v); acc[3][3] += __popcll(x3v ^ y3v);
            }
            __syncthreads();
        }

        // stage tile (rows = x, cols = y)
        #pragma unroll
        for (int i = 0; i < 4; i++)
            #pragma unroll
            for (int j = 0; j < 4; j++)
                stage[u + i][v + j] = __int2half_rn(M - 2 * acc[i][j]);
        __syncthreads();

        // pass 1: G[x0+row][y0+col], coalesced
        #pragma unroll
        for (int r = 0; r < 2; r++) {
            int idx = tid + 256 * r;        // 512 uint4
            int row = idx >> 3, seg = idx & 7;
            *(uint4*)&g_G[f][x0 + row][y0 + seg * 8] = *(const uint4*)&stage[row][seg * 8];
        }

        // pass 2: transposed G[y0+r][x0+..] (skip for diagonal tiles)
        if (tx != ty) {
            int r = tid >> 2, qd = tid & 3;     // r: 0..63, qd: 0..3 (16-col quarters)
            unsigned wds[8];
            #pragma unroll
            for (int k = 0; k < 8; k++) {
                unsigned short h0 = __half_as_ushort(stage[qd * 16 + 2 * k    ][r]);
                unsigned short h1 = __half_as_ushort(stage[qd * 16 + 2 * k + 1][r]);
                wds[k] = ((unsigned)h1 << 16) | h0;
            }
            uint4 lo = make_uint4(wds[0], wds[1], wds[2], wds[3]);
            uint4 hi = make_uint4(wds[4], wds[5], wds[6], wds[7]);
            *(uint4*)&g_G[f][y0 + r][x0 + qd * 16    ] = lo;
            *(uint4*)&g_G[f][y0 + r][x0 + qd * 16 + 8] = hi;
        }
        __syncthreads();
    }
}

// ---------------- fused iteration kernel ----------------
// upd = sign(new_est @ G[f]), pack to bits, diff flag, double-buffered est.
// grid = (F, 16, 2), block = 256 (8 warps). Block tile: 32(B) x 64(d), K = D.
__global__ void __launch_bounds__(256) k_iter(int t) {
    const int rbuf = t & 1, wbuf = (t & 1) ^ 1;
    __shared__ unsigned long long snew[32][WPD + 1];   // new_est bits, this f / b-half
    __shared__ __align__(16) __half shB[64][72];       // G chunk [d][k]
    __shared__ unsigned char sbytes[32][64];           // sign bytes

    int f  = blockIdx.x;
    int jd = blockIdx.y;               // d-tile (64 d per word)
    int b0 = blockIdx.z * 32;          // batch half
    int tid = threadIdx.x;
    int wid = tid >> 5, lane = tid & 31, g = lane >> 2, q = lane & 3;
    int mrow0 = (wid >> 2) * 16;       // 2 row groups of 16
    int ncol0 = (wid & 3) * 16;        // 4 col groups of 16

    // new_est bits: in ^ (xor over all f) ^ est_f, 512 words
    #pragma unroll
    for (int r = 0; r < 2; r++) {
        int idx = tid + 256 * r;
        int bl = idx >> 4, j = idx & 15;
        int b = b0 + bl;
        unsigned long long tot = g_in_bits[b][j];
        #pragma unroll
        for (int ff = 0; ff < F; ff++) tot ^= g_est[rbuf][b][ff][j];
        snew[bl][j] = tot ^ g_est[rbuf][b][f][j];
    }
    __syncthreads();

    float acc[2][4];
    #pragma unroll
    for (int i = 0; i < 2; i++)
        #pragma unroll
        for (int jj = 0; jj < 4; jj++) acc[i][jj] = 0.f;

    const int d0 = jd * 64;
    for (int kc = 0; kc < D; kc += 64) {
        // load G chunk: 64 rows (d) x 64 halves (k) = 512 uint4, 2 per thread
        #pragma unroll
        for (int r = 0; r < 2; r++) {
            int idx = tid + 256 * r;
            int row = idx >> 3, seg = idx & 7;
            *(uint4*)&shB[row][seg * 8] =
                *(const uint4*)&g_G[f][d0 + row][kc + seg * 8];
        }
        __syncthreads();
        unsigned long long w0 = snew[mrow0 + g][kc >> 6];
        unsigned long long w1 = snew[mrow0 + 8 + g][kc >> 6];
        #pragma unroll
        for (int kk = 0; kk < 64; kk += 16) {
            unsigned a0 = bits2h2((unsigned)(w0 >> (kk + q * 2)) & 3u);
            unsigned a1 = bits2h2((unsigned)(w1 >> (kk + q * 2)) & 3u);
            unsigned a2 = bits2h2((unsigned)(w0 >> (kk + 8 + q * 2)) & 3u);
            unsigned a3 = bits2h2((unsigned)(w1 >> (kk + 8 + q * 2)) & 3u);
            #pragma unroll
            for (int nt = 0; nt < 2; nt++) {
                unsigned b0v = *(const unsigned*)&shB[ncol0 + nt * 8 + g][kk + q * 2];
                unsigned b1v = *(const unsigned*)&shB[ncol0 + nt * 8 + g][kk + 8 + q * 2];
                mma16816(acc[nt], a0, a1, a2, a3, b0v, b1v);
            }
        }
        __syncthreads();
    }

    // epilogue: sign bytes -> smem
    int r0 = mrow0 + g;
    #pragma unroll
    for (int nt = 0; nt < 2; nt++) {
        int c0 = ncol0 + nt * 8 + q * 2;
        sbytes[r0    ][c0    ] = (unsigned char)(acc[nt][0] < 0.f);
        sbytes[r0    ][c0 + 1] = (unsigned char)(acc[nt][1] < 0.f);
        sbytes[r0 + 8][c0    ] = (unsigned char)(acc[nt][2] < 0.f);
        sbytes[r0 + 8][c0 + 1] = (unsigned char)(acc[nt][3] < 0.f);
    }
    __syncthreads();

    if (tid < 32) {
        const unsigned long long* q8 = (const unsigned long long*)sbytes[tid];
        unsigned long long w = 0ULL;
        #pragma unroll
        for (int s = 0; s < 8; s++) {
            unsigned long long x = q8[s];
            #pragma unroll
            for (int k = 0; k < 8; k++)
                w |= ((x >> (8 * k)) & 1ULL) << (8 * s + k);
        }
        int b = b0 + tid;
        bool diff = (w != g_est[rbuf][b][f][jd]);
        g_est[wbuf][b][f][jd] = w;
        unsigned bal = __ballot_sync(0xffffffffu, diff);
        if (lane == 0 && bal) atomicOr(&g_diff[t], 1);
    }
}

// ---------------- cleanup: partial argmax over m-chunks via atomicMax ----------------
// grid = (F, M/256, B/8), block = 256
__global__ void k_cleanup() {
    int f = blockIdx.x;
    int m = blockIdx.y * 256 + threadIdx.x;
    int b0 = blockIdx.z * 8;
    __shared__ unsigned long long sh[8][WPD];
    __shared__ int skey[8][33];
    if (threadIdx.x < 128) {
        int bb = threadIdx.x >> 4, j = threadIdx.x & 15;
        sh[bb][j] = g_est[FINAL_BUF][b0 + bb][f][j];
    }
    __syncthreads();
    int acc[8];
    #pragma unroll
    for (int i = 0; i < 8; i++) acc[i] = 0;
    #pragma unroll
    for (int j = 0; j < WPD; j++) {
        unsigned long long w = g_cb_bits[f][j][m];
        #pragma unroll
        for (int bb = 0; bb < 8; bb++) acc[bb] += __popcll(w ^ sh[bb][j]);
    }
    int lane = threadIdx.x & 31, wid = threadIdx.x >> 5;
    #pragma unroll
    for (int bb = 0; bb < 8; bb++) {
        int vv = D - 2 * acc[bb];
        int a = vv < 0 ? -vv : vv;
        int key = (a << 12) | (4095 - m);
        #pragma unroll
        for (int s = 16; s > 0; s >>= 1) {
            int o = __shfl_down_sync(0xffffffffu, key, s);
            if (o > key) key = o;
        }
        if (lane == 0) skey[bb][wid] = key;
    }
    __syncthreads();
    if (threadIdx.x < 8) {
        int bb = threadIdx.x;
        int best = skey[bb][0];
        #pragma unroll
        for (int w2 = 1; w2 < 8; w2++)
            if (skey[bb][w2] > best) best = skey[bb][w2];
        atomicMax(&g_key[(b0 + bb) * F + f], best);
    }
}

// ---------------- combined output kernel ----------------
__global__ void k_out(float* __restrict__ out_outcome,
                      float* __restrict__ out_est,
                      float* __restrict__ out_misc) {
    int idx = blockIdx.x * 256 + threadIdx.x;   // est: b*F*D + f*D + d
    if (out_est) {
        int d = idx & (D - 1);
        int f = (idx >> 10) & 3;
        int b = idx >> 12;
        unsigned long long w = g_est[FINAL_BUF][b][f][d >> 6];
        out_est[idx] = ((w >> (d & 63)) & 1ULL) ? -1.f : 1.f;
    }
    if (blockIdx.x == 0) {
        if (out_outcome && threadIdx.x < B * F)
            out_outcome[threadIdx.x] = (float)(4095 - (g_key[threadIdx.x] & 4095));
        if (out_misc && threadIdx.x == 0) {
            int iters = ITERS, conv = 0;
            for (int t = 0; t < ITERS; t++) {
                if (g_diff[t] == 0) { iters = t + 1; conv = 1; break; }
            }
            out_misc[0] = (float)iters;
            out_misc[1] = (float)conv;
        }
    }
}

// ---------------- launcher ----------------
extern "C" void kernel_launch(void* const* d_in, const int* in_sizes, int n_in,
                              void* d_out, int out_size) {
    const float* input = nullptr;
    const float* est0  = nullptr;
    const float* cb    = nullptr;
    for (int i = 0; i < n_in; i++) {
        if      (in_sizes[i] == B * D)     input = (const float*)d_in[i];
        else if (in_sizes[i] == B * F * D) est0  = (const float*)d_in[i];
        else if (in_sizes[i] == F * M * D) cb    = (const float*)d_in[i];
    }
    if (!input) input = (const float*)d_in[0];
    if (!est0)  est0  = (const float*)d_in[1];
    if (!cb)    cb    = (const float*)d_in[2];
    float* out = (float*)d_out;

    const int n_small = B * WPD + B * F * WPD + ITERS + B * F;
    k_pack_small<<<(n_small + 255) / 256, 256>>>(input, est0);
    k_pack_cb2<<<dim3(F, M / 8), 256>>>(cb);
    k_transpose_bits<<<dim3(F, M / 64), 256>>>();
    k_gram2<<<dim3(F, 68), 256>>>();

    for (int t = 0; t < ITERS; t++) {
        k_iter<<<dim3(F, D / 64, 2), 256>>>(t);
    }

    k_cleanup<<<dim3(F, M / 256, B / 8), 256>>>();

    // output layout (float32): order (outcome, est, iters, conv)
    const long long n_out = B * F;                 // 256
    const long long n_est = (long long)B * F * D;  // 262144
    long long off_outcome = -1, off_est = -1, off_misc = -1;
    if ((long long)out_size >= n_out + n_est + 2) {
        off_outcome = 0; off_est = n_out; off_misc = n_out + n_est;
    } else if ((long long)out_size == n_est) {
        off_est = 0;
    } else if ((long long)out_size == n_out) {
        off_outcome = 0;
    } else if ((long long)out_size == n_out + n_est) {
        off_outcome = 0; off_est = n_out;
    } else {
        off_outcome = 0;
    }

    k_out<<<(B * F * D) / 256, 256>>>(
        off_outcome >= 0 ? out + off_outcome : nullptr,
        off_est     >= 0 ? out + off_est     : nullptr,
        off_misc    >= 0 ? out + off_misc    : nullptr);
}

// round 11
// speedup vs baseline: 1.5061x; 1.1368x over previous
#include <cuda_runtime.h>
#include <cuda_fp16.h>
#include <cstdint>

#define B 64
#define F 4
#define M 4096
#define D 1024
#define ITERS 15
#define WPD 16   // 64-bit words per D-dim vector
#define WPM 64   // 64-bit words per M-dim vector
#define FINAL_BUF (ITERS & 1)

// ---------------- device scratch (no allocs allowed) ----------------
__device__ unsigned long long g_cb_bits[F][WPD][M];   // codebook bits over d, [f][word][m] (2 MB)
__device__ unsigned long long g_cbcol[F][D][WPM];     // codebook bits over m, [f][d][word] (2 MB)
__device__ __half             g_G[F][D][D];           // Gram matrix C^T C, exact even ints (8 MB)
__device__ unsigned long long g_in_bits[B][WPD];
__device__ unsigned long long g_est[2][B][F][WPD];    // double-buffered estimates (bit 1 = -1)
__device__ int                g_key[B * F];           // argmax keys (atomicMax)
__device__ int                g_diff[ITERS];          // per-iteration "changed" flags

// ---------------- helpers ----------------
__device__ __forceinline__ unsigned long long pack64(const float* p) {
    unsigned long long w = 0ULL;
    #pragma unroll
    for (int t = 0; t < 16; t++) {
        float4 v = reinterpret_cast<const float4*>(p)[t];
        w |= ((unsigned long long)(v.x < 0.f)) << (4 * t + 0);
        w |= ((unsigned long long)(v.y < 0.f)) << (4 * t + 1);
        w |= ((unsigned long long)(v.z < 0.f)) << (4 * t + 2);
        w |= ((unsigned long long)(v.w < 0.f)) << (4 * t + 3);
    }
    return w;
}

__device__ __forceinline__ void mma16816(float* c,
                                         unsigned a0, unsigned a1, unsigned a2, unsigned a3,
                                         unsigned b0, unsigned b1) {
    asm volatile(
        "mma.sync.aligned.m16n8k16.row.col.f32.f16.f16.f32 "
        "{%0,%1,%2,%3}, {%4,%5,%6,%7}, {%8,%9}, {%0,%1,%2,%3};"
        : "+f"(c[0]), "+f"(c[1]), "+f"(c[2]), "+f"(c[3])
        : "r"(a0), "r"(a1), "r"(a2), "r"(a3), "r"(b0), "r"(b1));
}

// bits (2 low bits, 1 = negative) -> packed half2 {+-1, +-1}
__device__ __forceinline__ unsigned bits2h2(unsigned bits) {
    return 0x3C003C00u ^ ((bits & 1u) << 15) ^ ((bits & 2u) << 30);
}

// ---------------- packing kernels ----------------
__global__ void k_pack_small(const float* __restrict__ input,
                             const float* __restrict__ est0) {
    int idx = blockIdx.x * 256 + threadIdx.x;
    const int base = B * WPD + B * F * WPD;
    if (idx < B * WPD) {
        int b = idx >> 4, j = idx & 15;
        g_in_bits[b][j] = pack64(input + b * D + j * 64);
    } else if (idx < base) {
        int w = idx - B * WPD;
        int b = w >> 6, f = (w >> 4) & 3, j = w & 15;
        g_est[0][b][f][j] = pack64(est0 + (size_t)(b * F + f) * D + j * 64);
    } else if (idx < base + ITERS) {
        g_diff[idx - base] = 0;
    } else if (idx < base + ITERS + B * F) {
        g_key[idx - base - ITERS] = -1;
    }
}

// fused: pack codebook rows to bits (ballot, coalesced) AND transpose to g_cbcol.
// grid = (F, M/64), block = 256 (8 warps); each block owns 64 m-rows.
__global__ void __launch_bounds__(256) k_pack_cb3(const float* __restrict__ cb) {
    __shared__ unsigned long long sm[64][17];   // [m_local][j]
    int f  = blockIdx.x;
    int jm = blockIdx.y;
    int wid = threadIdx.x >> 5, lane = threadIdx.x & 31;

    #pragma unroll
    for (int r = 0; r < 8; r++) {
        int ml = wid * 8 + r;
        int m = jm * 64 + ml;
        const float* row = cb + ((size_t)(f * M + m)) * D;
        #pragma unroll
        for (int j = 0; j < WPD; j++) {
            unsigned lo = __ballot_sync(0xffffffffu, row[j * 64 + lane] < 0.f);
            unsigned hi = __ballot_sync(0xffffffffu, row[j * 64 + 32 + lane] < 0.f);
            if (lane == 0) {
                unsigned long long w = ((unsigned long long)hi << 32) | lo;
                g_cb_bits[f][j][m] = w;
                sm[ml][j] = w;
            }
        }
    }
    __syncthreads();

    // transpose: bit k of sm[*][j] -> m-word jm of g_cbcol[f][d= j*64+bp]
    for (int i = 0; i < 128; i++) {
        int d = wid * 128 + i;
        int j = d >> 6, bp = d & 63;
        unsigned lo = __ballot_sync(0xffffffffu,
            (unsigned)((sm[lane][j] >> bp) & 1ULL));
        unsigned hi = __ballot_sync(0xffffffffu,
            (unsigned)((sm[lane + 32][j] >> bp) & 1ULL));
        if (lane == 0)
            g_cbcol[f][d][jm] = ((unsigned long long)hi << 32) | lo;
    }
}

// ---------------- Gram: symmetric 64x64 tiles, 4x4/thread, stride-16 rows ----------------
// Conflict-free LDS: thread (tid>>4, tid&15) owns x-rows {u,u+16,u+32,u+48},
// y-rows {v,v+16,v+32,v+48}; pad 17 words -> 16 consecutive 8B banks per access.
__global__ void __launch_bounds__(256) k_gram2() {
    __shared__ unsigned long long shX[64][17];
    __shared__ unsigned long long shY[64][17];
    __shared__ __half stage[64][72];

    int f = blockIdx.x;
    int p = blockIdx.y;                 // triangular pair index, 136 per f
    int tx = 0;
    while (p >= 16 - tx) { p -= 16 - tx; tx++; }
    int ty = tx + p;
    int x0 = tx * 64, y0 = ty * 64;

    int tid = threadIdx.x;
    int u = tid >> 4;                   // x base row (0..15), rows u+16i
    int v = tid & 15;                   // y base row (0..15), rows v+16j

    int acc[4][4];
    #pragma unroll
    for (int i = 0; i < 4; i++)
        #pragma unroll
        for (int j = 0; j < 4; j++) acc[i][j] = 0;

    for (int kc = 0; kc < WPM; kc += 16) {
        #pragma unroll
        for (int r = 0; r < 4; r++) {
            int idx = tid + 256 * r;    // 1024 words
            int row = idx >> 4, w = idx & 15;
            shX[row][w] = g_cbcol[f][x0 + row][kc + w];
            shY[row][w] = g_cbcol[f][y0 + row][kc + w];
        }
        __syncthreads();
        #pragma unroll
        for (int w = 0; w < 16; w++) {
            unsigned long long x0v = shX[u     ][w];
            unsigned long long x1v = shX[u + 16][w];
            unsigned long long x2v = shX[u + 32][w];
            unsigned long long x3v = shX[u + 48][w];
            unsigned long long y0v = shY[v     ][w];
            unsigned long long y1v = shY[v + 16][w];
            unsigned long long y2v = shY[v + 32][w];
            unsigned long long y3v = shY[v + 48][w];
            acc[0][0] += __popcll(x0v ^ y0v); acc[0][1] += __popcll(x0v ^ y1v);
            acc[0][2] += __popcll(x0v ^ y2v); acc[0][3] += __popcll(x0v ^ y3v);
            acc[1][0] += __popcll(x1v ^ y0v); acc[1][1] += __popcll(x1v ^ y1v);
            acc[1][2] += __popcll(x1v ^ y2v); acc[1][3] += __popcll(x1v ^ y3v);
            acc[2][0] += __popcll(x2v ^ y0v); acc[2][1] += __popcll(x2v ^ y1v);
            acc[2][2] += __popcll(x2v ^ y2v); acc[2][3] += __popcll(x2v ^ y3v);
            acc[3][0] += __popcll(x3v ^ y0v); acc[3][1] += __popcll(x3v ^ y1v);
            acc[3][2] += __popcll(x3v ^ y2v); acc[3][3] += __popcll(x3v ^ y3v);
        }
        __syncthreads();
    }

    // stage tile (rows = x, cols = y)
    #pragma unroll
    for (int i = 0; i < 4; i++)
        #pragma unroll
        for (int j = 0; j < 4; j++)
            stage[u + 16 * i][v + 16 * j] = __int2half_rn(M - 2 * acc[i][j]);
    __syncthreads();

    // pass 1: G[x0+row][y0+col], coalesced
    #pragma unroll
    for (int r = 0; r < 2; r++) {
        int idx = tid + 256 * r;        // 512 uint4
        int row = idx >> 3, seg = idx & 7;
        *(uint4*)&g_G[f][x0 + row][y0 + seg * 8] = *(const uint4*)&stage[row][seg * 8];
    }

    // pass 2: transposed G[y0+r][x0+..] (skip for diagonal tiles)
    if (tx != ty) {
        int r = tid >> 2, qd = tid & 3;     // r: 0..63, qd: 0..3 (16-col quarters)
        unsigned wds[8];
        #pragma unroll
        for (int k = 0; k < 8; k++) {
            unsigned short h0 = __half_as_ushort(stage[qd * 16 + 2 * k    ][r]);
            unsigned short h1 = __half_as_ushort(stage[qd * 16 + 2 * k + 1][r]);
            wds[k] = ((unsigned)h1 << 16) | h0;
        }
        uint4 lo = make_uint4(wds[0], wds[1], wds[2], wds[3]);
        uint4 hi = make_uint4(wds[4], wds[5], wds[6], wds[7]);
        *(uint4*)&g_G[f][y0 + r][x0 + qd * 16    ] = lo;
        *(uint4*)&g_G[f][y0 + r][x0 + qd * 16 + 8] = hi;
    }
}

// ---------------- fused iteration kernel ----------------
// upd = sign(new_est @ G[f]), pack to bits, diff flag, double-buffered est.
// grid = (F, 16, 2), block = 256 (8 warps). Block tile: 32(B) x 64(d), K = D (chunks of 128).
__global__ void __launch_bounds__(256) k_iter(int t) {
    const int rbuf = t & 1, wbuf = (t & 1) ^ 1;
    __shared__ unsigned long long snew[32][WPD + 1];   // new_est bits, this f / b-half
    __shared__ __align__(16) __half shB[64][136];      // G chunk [d][k], 128 k + pad
    __shared__ unsigned char sbytes[32][64];           // sign bytes

    int f  = blockIdx.x;
    int jd = blockIdx.y;               // d-tile (64 d per word)
    int b0 = blockIdx.z * 32;          // batch half
    int tid = threadIdx.x;
    int wid = tid >> 5, lane = tid & 31, g = lane >> 2, q = lane & 3;
    int mrow0 = (wid >> 2) * 16;       // 2 row groups of 16
    int ncol0 = (wid & 3) * 16;        // 4 col groups of 16

    // new_est bits: in ^ (xor over all f) ^ est_f, 512 words
    #pragma unroll
    for (int r = 0; r < 2; r++) {
        int idx = tid + 256 * r;
        int bl = idx >> 4, j = idx & 15;
        int b = b0 + bl;
        unsigned long long tot = g_in_bits[b][j];
        #pragma unroll
        for (int ff = 0; ff < F; ff++) tot ^= g_est[rbuf][b][ff][j];
        snew[bl][j] = tot ^ g_est[rbuf][b][f][j];
    }
    __syncthreads();

    float acc[2][4];
    #pragma unroll
    for (int i = 0; i < 2; i++)
        #pragma unroll
        for (int jj = 0; jj < 4; jj++) acc[i][jj] = 0.f;

    const int d0 = jd * 64;
    for (int kc = 0; kc < D; kc += 128) {
        // load G chunk: 64 rows (d) x 128 halves (k) = 1024 uint4, 4 per thread
        #pragma unroll
        for (int r = 0; r < 4; r++) {
            int idx = tid + 256 * r;
            int row = idx >> 4, seg = idx & 15;
            *(uint4*)&shB[row][seg * 8] =
                *(const uint4*)&g_G[f][d0 + row][kc + seg * 8];
        }
        __syncthreads();
        #pragma unroll
        for (int sub = 0; sub < 2; sub++) {
            unsigned long long w0 = snew[mrow0 + g][(kc >> 6) + sub];
            unsigned long long w1 = snew[mrow0 + 8 + g][(kc >> 6) + sub];
            #pragma unroll
            for (int kk = 0; kk < 64; kk += 16) {
                unsigned a0 = bits2h2((unsigned)(w0 >> (kk + q * 2)) & 3u);
                unsigned a1 = bits2h2((unsigned)(w1 >> (kk + q * 2)) & 3u);
                unsigned a2 = bits2h2((unsigned)(w0 >> (kk + 8 + q * 2)) & 3u);
                unsigned a3 = bits2h2((unsigned)(w1 >> (kk + 8 + q * 2)) & 3u);
                #pragma unroll
                for (int nt = 0; nt < 2; nt++) {
                    unsigned b0v = *(const unsigned*)&shB[ncol0 + nt * 8 + g][sub * 64 + kk + q * 2];
                    unsigned b1v = *(const unsigned*)&shB[ncol0 + nt * 8 + g][sub * 64 + kk + 8 + q * 2];
                    mma16816(acc[nt], a0, a1, a2, a3, b0v, b1v);
                }
            }
        }
        __syncthreads();
    }

    // epilogue: sign bytes -> smem
    int r0 = mrow0 + g;
    #pragma unroll
    for (int nt = 0; nt < 2; nt++) {
        int c0 = ncol0 + nt * 8 + q * 2;
        sbytes[r0    ][c0    ] = (unsigned char)(acc[nt][0] < 0.f);
        sbytes[r0    ][c0 + 1] = (unsigned char)(acc[nt][1] < 0.f);
        sbytes[r0 + 8][c0    ] = (unsigned char)(acc[nt][2] < 0.f);
        sbytes[r0 + 8][c0 + 1] = (unsigned char)(acc[nt][3] < 0.f);
    }
    __syncthreads();

    if (tid < 32) {
        const unsigned long long* q8 = (const unsigned long long*)sbytes[tid];
        unsigned long long w = 0ULL;
        #pragma unroll
        for (int s = 0; s < 8; s++) {
            unsigned long long x = q8[s];
            #pragma unroll
            for (int k = 0; k < 8; k++)
                w |= ((x >> (8 * k)) & 1ULL) << (8 * s + k);
        }
        int b = b0 + tid;
        bool diff = (w != g_est[rbuf][b][f][jd]);
        g_est[wbuf][b][f][jd] = w;
        unsigned bal = __ballot_sync(0xffffffffu, diff);
        if (lane == 0 && bal) atomicOr(&g_diff[t], 1);
    }
}

// ---------------- cleanup: partial argmax over m-chunks via atomicMax ----------------
// grid = (F, M/256, B/8), block = 256
__global__ void k_cleanup() {
    int f = blockIdx.x;
    int m = blockIdx.y * 256 + threadIdx.x;
    int b0 = blockIdx.z * 8;
    __shared__ unsigned long long sh[8][WPD];
    __shared__ int skey[8][33];
    if (threadIdx.x < 128) {
        int bb = threadIdx.x >> 4, j = threadIdx.x & 15;
        sh[bb][j] = g_est[FINAL_BUF][b0 + bb][f][j];
    }
    __syncthreads();
    int acc[8];
    #pragma unroll
    for (int i = 0; i < 8; i++) acc[i] = 0;
    #pragma unroll
    for (int j = 0; j < WPD; j++) {
        unsigned long long w = g_cb_bits[f][j][m];
        #pragma unroll
        for (int bb = 0; bb < 8; bb++) acc[bb] += __popcll(w ^ sh[bb][j]);
    }
    int lane = threadIdx.x & 31, wid = threadIdx.x >> 5;
    #pragma unroll
    for (int bb = 0; bb < 8; bb++) {
        int vv = D - 2 * acc[bb];
        int a = vv < 0 ? -vv : vv;
        int key = (a << 12) | (4095 - m);
        #pragma unroll
        for (int s = 16; s > 0; s >>= 1) {
            int o = __shfl_down_sync(0xffffffffu, key, s);
            if (o > key) key = o;
        }
        if (lane == 0) skey[bb][wid] = key;
    }
    __syncthreads();
    if (threadIdx.x < 8) {
        int bb = threadIdx.x;
        int best = skey[bb][0];
        #pragma unroll
        for (int w2 = 1; w2 < 8; w2++)
            if (skey[bb][w2] > best) best = skey[bb][w2];
        atomicMax(&g_key[(b0 + bb) * F + f], best);
    }
}

// ---------------- combined output kernel ----------------
__global__ void k_out(float* __restrict__ out_outcome,
                      float* __restrict__ out_est,
                      float* __restrict__ out_misc) {
    int idx = blockIdx.x * 256 + threadIdx.x;   // est: b*F*D + f*D + d
    if (out_est) {
        int d = idx & (D - 1);
        int f = (idx >> 10) & 3;
        int b = idx >> 12;
        unsigned long long w = g_est[FINAL_BUF][b][f][d >> 6];
        out_est[idx] = ((w >> (d & 63)) & 1ULL) ? -1.f : 1.f;
    }
    if (blockIdx.x == 0) {
        if (out_outcome && threadIdx.x < B * F)
            out_outcome[threadIdx.x] = (float)(4095 - (g_key[threadIdx.x] & 4095));
        if (out_misc && threadIdx.x == 0) {
            int iters = ITERS, conv = 0;
            for (int t = 0; t < ITERS; t++) {
                if (g_diff[t] == 0) { iters = t + 1; conv = 1; break; }
            }
            out_misc[0] = (float)iters;
            out_misc[1] = (float)conv;
        }
    }
}

// ---------------- launcher ----------------
extern "C" void kernel_launch(void* const* d_in, const int* in_sizes, int n_in,
                              void* d_out, int out_size) {
    const float* input = nullptr;
    const float* est0  = nullptr;
    const float* cb    = nullptr;
    for (int i = 0; i < n_in; i++) {
        if      (in_sizes[i] == B * D)     input = (const float*)d_in[i];
        else if (in_sizes[i] == B * F * D) est0  = (const float*)d_in[i];
        else if (in_sizes[i] == F * M * D) cb    = (const float*)d_in[i];
    }
    if (!input) input = (const float*)d_in[0];
    if (!est0)  est0  = (const float*)d_in[1];
    if (!cb)    cb    = (const float*)d_in[2];
    float* out = (float*)d_out;

    const int n_small = B * WPD + B * F * WPD + ITERS + B * F;
    k_pack_small<<<(n_small + 255) / 256, 256>>>(input, est0);
    k_pack_cb3<<<dim3(F, M / 64), 256>>>(cb);
    k_gram2<<<dim3(F, 136), 256>>>();

    for (int t = 0; t < ITERS; t++) {
        k_iter<<<dim3(F, D / 64, 2), 256>>>(t);
    }

    k_cleanup<<<dim3(F, M / 256, B / 8), 256>>>();

    // output layout (float32): order (outcome, est, iters, conv)
    const long long n_out = B * F;                 // 256
    const long long n_est = (long long)B * F * D;  // 262144
    long long off_outcome = -1, off_est = -1, off_misc = -1;
    if ((long long)out_size >= n_out + n_est + 2) {
        off_outcome = 0; off_est = n_out; off_misc = n_out + n_est;
    } else if ((long long)out_size == n_est) {
        off_est = 0;
    } else if ((long long)out_size == n_out) {
        off_outcome = 0;
    } else if ((long long)out_size == n_out + n_est) {
        off_outcome = 0; off_est = n_out;
    } else {
        off_outcome = 0;
    }

    k_out<<<(B * F * D) / 256, 256>>>(
        off_outcome >= 0 ? out + off_outcome : nullptr,
        off_est     >= 0 ? out + off_est     : nullptr,
        off_misc    >= 0 ? out + off_misc    : nullptr);
}

// round 12
// speedup vs baseline: 1.6547x; 1.0986x over previous
#include <cuda_runtime.h>
#include <cuda_fp16.h>
#include <cstdint>

#define B 64
#define F 4
#define M 4096
#define D 1024
#define ITERS 15
#define WPD 16   // 64-bit words per D-dim vector
#define WPM 64   // 64-bit words per M-dim vector
#define FINAL_BUF (ITERS & 1)
#define NBLK 128 // persistent blocks; 138KB smem -> 1/SM, 128 < 148 SMs

// dynamic smem layout for k_mega
#define SG_STRIDE   1032                   // halves per row (1024 + 8 pad)
#define SG_BYTES    (64 * SG_STRIDE * 2)   // 132096
#define SNEW_OFF    SG_BYTES
#define SNEW_BYTES  (32 * 17 * 8)          // 4352
#define SBYTES_OFF  (SNEW_OFF + SNEW_BYTES)
#define SMEM_MEGA   (SBYTES_OFF + 32 * 64) // 138496

// ---------------- device scratch (no allocs allowed) ----------------
__device__ unsigned long long g_cb_bits[F][WPD][M];   // codebook bits over d (2 MB)
__device__ unsigned long long g_cbcol[F][D][WPM];     // codebook bits over m (2 MB)
__device__ __half             g_G[F][D][D];           // Gram matrix C^T C, exact even ints (8 MB)
__device__ unsigned long long g_in_bits[B][WPD];
__device__ unsigned long long g_est[2][B][F][WPD];    // double-buffered estimates (bit 1 = -1)
__device__ int                g_key[B * F];           // argmax keys (atomicMax)
__device__ int                g_diff[ITERS];          // per-iteration "changed" flags
__device__ unsigned           g_bar_count;            // grid barrier state
__device__ unsigned           g_bar_gen;

// ---------------- helpers ----------------
__device__ __forceinline__ unsigned long long pack64(const float* p) {
    unsigned long long w = 0ULL;
    #pragma unroll
    for (int t = 0; t < 16; t++) {
        float4 v = reinterpret_cast<const float4*>(p)[t];
        w |= ((unsigned long long)(v.x < 0.f)) << (4 * t + 0);
        w |= ((unsigned long long)(v.y < 0.f)) << (4 * t + 1);
        w |= ((unsigned long long)(v.z < 0.f)) << (4 * t + 2);
        w |= ((unsigned long long)(v.w < 0.f)) << (4 * t + 3);
    }
    return w;
}

__device__ __forceinline__ void mma16816(float* c,
                                         unsigned a0, unsigned a1, unsigned a2, unsigned a3,
                                         unsigned b0, unsigned b1) {
    asm volatile(
        "mma.sync.aligned.m16n8k16.row.col.f32.f16.f16.f32 "
        "{%0,%1,%2,%3}, {%4,%5,%6,%7}, {%8,%9}, {%0,%1,%2,%3};"
        : "+f"(c[0]), "+f"(c[1]), "+f"(c[2]), "+f"(c[3])
        : "r"(a0), "r"(a1), "r"(a2), "r"(a3), "r"(b0), "r"(b1));
}

__device__ __forceinline__ unsigned bits2h2(unsigned bits) {
    return 0x3C003C00u ^ ((bits & 1u) << 15) ^ ((bits & 2u) << 30);
}

__device__ __forceinline__ void grid_barrier() {
    __syncthreads();
    if (threadIdx.x == 0) {
        __threadfence();
        unsigned gen = atomicAdd(&g_bar_gen, 0u);
        if (atomicAdd(&g_bar_count, 1u) == NBLK - 1) {
            atomicExch(&g_bar_count, 0u);
            atomicAdd(&g_bar_gen, 1u);
        } else {
            while (atomicAdd(&g_bar_gen, 0u) == gen) {}
        }
        __threadfence();
    }
    __syncthreads();
}

// ---------------- fused packing: codebook bits + transpose + small inputs ----------------
// grid = (F, M/64), block = 256 (8 warps); each block owns 64 m-rows.
__global__ void __launch_bounds__(256) k_pack_all(const float* __restrict__ cb,
                                                  const float* __restrict__ input,
                                                  const float* __restrict__ est0) {
    __shared__ unsigned long long sm[64][17];   // [m_local][j]
    int f  = blockIdx.x;
    int jm = blockIdx.y;
    int wid = threadIdx.x >> 5, lane = threadIdx.x & 31;

    // small-input packing spread over first 22 blocks of f == 0
    if (f == 0 && jm < 22) {
        int idx = jm * 256 + threadIdx.x;
        if (idx < 1024) {                       // B*WPD
            int b = idx >> 4, j = idx & 15;
            g_in_bits[b][j] = pack64(input + b * D + j * 64);
        } else if (idx < 5120) {                // + B*F*WPD
            int w = idx - 1024;
            int b = w >> 6, ff = (w >> 4) & 3, j = w & 15;
            g_est[0][b][ff][j] = pack64(est0 + (size_t)(b * F + ff) * D + j * 64);
        } else if (idx < 5120 + ITERS) {
            g_diff[idx - 5120] = 0;
        } else if (idx < 5135 + B * F) {
            g_key[idx - 5135] = -1;
        } else if (idx == 5135 + B * F) {
            g_bar_count = 0u;
            g_bar_gen = 0u;
        }
    }

    #pragma unroll
    for (int r = 0; r < 8; r++) {
        int ml = wid * 8 + r;
        int m = jm * 64 + ml;
        const float* row = cb + ((size_t)(f * M + m)) * D;
        #pragma unroll
        for (int j = 0; j < WPD; j++) {
            unsigned lo = __ballot_sync(0xffffffffu, row[j * 64 + lane] < 0.f);
            unsigned hi = __ballot_sync(0xffffffffu, row[j * 64 + 32 + lane] < 0.f);
            if (lane == 0) {
                unsigned long long w = ((unsigned long long)hi << 32) | lo;
                g_cb_bits[f][j][m] = w;
                sm[ml][j] = w;
            }
        }
    }
    __syncthreads();

    for (int i = 0; i < 128; i++) {
        int d = wid * 128 + i;
        int j = d >> 6, bp = d & 63;
        unsigned lo = __ballot_sync(0xffffffffu,
            (unsigned)((sm[lane][j] >> bp) & 1ULL));
        unsigned hi = __ballot_sync(0xffffffffu,
            (unsigned)((sm[lane + 32][j] >> bp) & 1ULL));
        if (lane == 0)
            g_cbcol[f][d][jm] = ((unsigned long long)hi << 32) | lo;
    }
}

// ---------------- Gram: symmetric 64x64 tiles, 4x4/thread, stride-16 rows ----------------
__global__ void __launch_bounds__(256) k_gram2() {
    __shared__ unsigned long long shX[64][17];
    __shared__ unsigned long long shY[64][17];
    __shared__ __half stage[64][72];

    int f = blockIdx.x;
    int p = blockIdx.y;                 // triangular pair index, 136 per f
    int tx = 0;
    while (p >= 16 - tx) { p -= 16 - tx; tx++; }
    int ty = tx + p;
    int x0 = tx * 64, y0 = ty * 64;

    int tid = threadIdx.x;
    int u = tid >> 4;                   // x base row, rows u+16i
    int v = tid & 15;                   // y base row, rows v+16j

    int acc[4][4];
    #pragma unroll
    for (int i = 0; i < 4; i++)
        #pragma unroll
        for (int j = 0; j < 4; j++) acc[i][j] = 0;

    for (int kc = 0; kc < WPM; kc += 16) {
        #pragma unroll
        for (int r = 0; r < 4; r++) {
            int idx = tid + 256 * r;
            int row = idx >> 4, w = idx & 15;
            shX[row][w] = g_cbcol[f][x0 + row][kc + w];
            shY[row][w] = g_cbcol[f][y0 + row][kc + w];
        }
        __syncthreads();
        #pragma unroll
        for (int w = 0; w < 16; w++) {
            unsigned long long x0v = shX[u     ][w];
            unsigned long long x1v = shX[u + 16][w];
            unsigned long long x2v = shX[u + 32][w];
            unsigned long long x3v = shX[u + 48][w];
            unsigned long long y0v = shY[v     ][w];
            unsigned long long y1v = shY[v + 16][w];
            unsigned long long y2v = shY[v + 32][w];
            unsigned long long y3v = shY[v + 48][w];
            acc[0][0] += __popcll(x0v ^ y0v); acc[0][1] += __popcll(x0v ^ y1v);
            acc[0][2] += __popcll(x0v ^ y2v); acc[0][3] += __popcll(x0v ^ y3v);
            acc[1][0] += __popcll(x1v ^ y0v); acc[1][1] += __popcll(x1v ^ y1v);
            acc[1][2] += __popcll(x1v ^ y2v); acc[1][3] += __popcll(x1v ^ y3v);
            acc[2][0] += __popcll(x2v ^ y0v); acc[2][1] += __popcll(x2v ^ y1v);
            acc[2][2] += __popcll(x2v ^ y2v); acc[2][3] += __popcll(x2v ^ y3v);
            acc[3][0] += __popcll(x3v ^ y0v); acc[3][1] += __popcll(x3v ^ y1v);
            acc[3][2] += __popcll(x3v ^ y2v); acc[3][3] += __popcll(x3v ^ y3v);
        }
        __syncthreads();
    }

    #pragma unroll
    for (int i = 0; i < 4; i++)
        #pragma unroll
        for (int j = 0; j < 4; j++)
            stage[u + 16 * i][v + 16 * j] = __int2half_rn(M - 2 * acc[i][j]);
    __syncthreads();

    #pragma unroll
    for (int r = 0; r < 2; r++) {
        int idx = tid + 256 * r;
        int row = idx >> 3, seg = idx & 7;
        *(uint4*)&g_G[f][x0 + row][y0 + seg * 8] = *(const uint4*)&stage[row][seg * 8];
    }

    if (tx != ty) {
        int r = tid >> 2, qd = tid & 3;
        unsigned wds[8];
        #pragma unroll
        for (int k = 0; k < 8; k++) {
            unsigned short h0 = __half_as_ushort(stage[qd * 16 + 2 * k    ][r]);
            unsigned short h1 = __half_as_ushort(stage[qd * 16 + 2 * k + 1][r]);
            wds[k] = ((unsigned)h1 << 16) | h0;
        }
        uint4 lo = make_uint4(wds[0], wds[1], wds[2], wds[3]);
        uint4 hi = make_uint4(wds[4], wds[5], wds[6], wds[7]);
        *(uint4*)&g_G[f][y0 + r][x0 + qd * 16    ] = lo;
        *(uint4*)&g_G[f][y0 + r][x0 + qd * 16 + 8] = hi;
    }
}

// ---------------- persistent mega: G tile resident in smem, 15 iters + cleanup + outputs ----
// grid = (F, 16, 2) = 128 blocks, block = 256 (8 warps). Tile: 32(B) x 64(d), K = D from smem.
__global__ void __launch_bounds__(256) k_mega(float* __restrict__ out_outcome,
                                              float* __restrict__ out_est,
                                              float* __restrict__ out_misc) {
    extern __shared__ char smem[];
    __half (*sG)[SG_STRIDE] = (__half(*)[SG_STRIDE])smem;
    unsigned long long (*snew)[17] = (unsigned long long(*)[17])(smem + SNEW_OFF);
    unsigned char (*sbytes)[64] = (unsigned char(*)[64])(smem + SBYTES_OFF);

    const int f  = blockIdx.x;
    const int jd = blockIdx.y;
    const int bz = blockIdx.z;
    const int b0 = bz * 32;
    const int tid = threadIdx.x;
    const int wid = tid >> 5, lane = tid & 31, g = lane >> 2, q = lane & 3;
    const int mrow0 = (wid >> 2) * 16;       // 2 row groups of 16
    const int ncol0 = (wid & 3) * 16;        // 4 col groups of 16
    const int d0 = jd * 64;

    // load this block's G tile (64 d-rows x 1024 k) into smem ONCE
    #pragma unroll
    for (int r = 0; r < 32; r++) {
        int idx = tid + 256 * r;          // 8192 uint4
        int row = idx >> 7, seg = idx & 127;
        *(uint4*)&sG[row][seg * 8] = *(const uint4*)&g_G[f][d0 + row][seg * 8];
    }
    __syncthreads();

    for (int t = 0; t < ITERS; t++) {
        const int rbuf = t & 1, wbuf = rbuf ^ 1;

        // new_est bits: in ^ (xor over all f) ^ est_f
        #pragma unroll
        for (int r = 0; r < 2; r++) {
            int idx = tid + 256 * r;
            int bl = idx >> 4, j = idx & 15;
            int b = b0 + bl;
            unsigned long long tot = g_in_bits[b][j];
            #pragma unroll
            for (int ff = 0; ff < F; ff++) tot ^= g_est[rbuf][b][ff][j];
            snew[bl][j] = tot ^ g_est[rbuf][b][f][j];
        }
        __syncthreads();

        float acc[2][4];
        #pragma unroll
        for (int i = 0; i < 2; i++)
            #pragma unroll
            for (int jj = 0; jj < 4; jj++) acc[i][jj] = 0.f;

        #pragma unroll 4
        for (int wj = 0; wj < 16; wj++) {
            unsigned long long w0 = snew[mrow0 + g][wj];
            unsigned long long w1 = snew[mrow0 + 8 + g][wj];
            #pragma unroll
            for (int kk = 0; kk < 64; kk += 16) {
                unsigned a0 = bits2h2((unsigned)(w0 >> (kk + q * 2)) & 3u);
                unsigned a1 = bits2h2((unsigned)(w1 >> (kk + q * 2)) & 3u);
                unsigned a2 = bits2h2((unsigned)(w0 >> (kk + 8 + q * 2)) & 3u);
                unsigned a3 = bits2h2((unsigned)(w1 >> (kk + 8 + q * 2)) & 3u);
                #pragma unroll
                for (int nt = 0; nt < 2; nt++) {
                    unsigned b0v = *(const unsigned*)&sG[ncol0 + nt * 8 + g][wj * 64 + kk + q * 2];
                    unsigned b1v = *(const unsigned*)&sG[ncol0 + nt * 8 + g][wj * 64 + kk + 8 + q * 2];
                    mma16816(acc[nt], a0, a1, a2, a3, b0v, b1v);
                }
            }
        }

        // epilogue: sign bytes
        int r0 = mrow0 + g;
        #pragma unroll
        for (int nt = 0; nt < 2; nt++) {
            int c0 = ncol0 + nt * 8 + q * 2;
            sbytes[r0    ][c0    ] = (unsigned char)(acc[nt][0] < 0.f);
            sbytes[r0    ][c0 + 1] = (unsigned char)(acc[nt][1] < 0.f);
            sbytes[r0 + 8][c0    ] = (unsigned char)(acc[nt][2] < 0.f);
            sbytes[r0 + 8][c0 + 1] = (unsigned char)(acc[nt][3] < 0.f);
        }
        __syncthreads();

        if (tid < 32) {
            const unsigned long long* q8 = (const unsigned long long*)sbytes[tid];
            unsigned long long w = 0ULL;
            #pragma unroll
            for (int s = 0; s < 8; s++) {
                unsigned long long x = q8[s];
                #pragma unroll
                for (int k = 0; k < 8; k++)
                    w |= ((x >> (8 * k)) & 1ULL) << (8 * s + k);
            }
            int b = b0 + tid;
            bool diff = (w != g_est[rbuf][b][f][jd]);
            g_est[wbuf][b][f][jd] = w;
            unsigned bal = __ballot_sync(0xffffffffu, diff);
            if (lane == 0 && bal) atomicOr(&g_diff[t], 1);
        }
        grid_barrier();
    }

    // ---- cleanup: partial argmax over this block's 128-m chunk, all 64 b (reuse sG space) ----
    {
        unsigned long long (*sest)[WPD] = (unsigned long long(*)[WPD])smem;
        #pragma unroll
        for (int r = 0; r < 4; r++) {
            int idx = tid + 256 * r;
            int b = idx >> 4, j = idx & 15;
            sest[b][j] = g_est[FINAL_BUF][b][f][j];
        }
        __syncthreads();

        int m = (jd * 2 + bz) * 128 + (tid & 127);
        int bh = (tid >> 7) * 32;
        for (int bb = 0; bb < 32; bb++) {
            int b = bh + bb;
            int acc = 0;
            #pragma unroll
            for (int j = 0; j < WPD; j++)
                acc += __popcll(g_cb_bits[f][j][m] ^ sest[b][j]);
            int vv = D - 2 * acc;
            int a = vv < 0 ? -vv : vv;
            int key = (a << 12) | (4095 - m);
            #pragma unroll
            for (int s = 16; s > 0; s >>= 1) {
                int o = __shfl_down_sync(0xffffffffu, key, s);
                if (o > key) key = o;
            }
            if (lane == 0) atomicMax(&g_key[b * F + f], key);
        }
    }

    // ---- est output: 2048 floats per block ----
    if (out_est) {
        int blk = (f * 16 + jd) * 2 + bz;
        int base = blk * 2048;
        #pragma unroll
        for (int r = 0; r < 8; r++) {
            int idx = base + tid + 256 * r;    // b*F*D + f*D + d
            int d = idx & (D - 1);
            int ff = (idx >> 10) & 3;
            int b = idx >> 12;
            unsigned long long w = g_est[FINAL_BUF][b][ff][d >> 6];
            out_est[idx] = ((w >> (d & 63)) & 1ULL) ? -1.f : 1.f;
        }
    }

    grid_barrier();

    if (f == 0 && jd == 0 && bz == 0) {
        if (out_outcome && tid < B * F)
            out_outcome[tid] = (float)(4095 - (g_key[tid] & 4095));
        if (out_misc && tid == 0) {
            int iters = ITERS, conv = 0;
            for (int t = 0; t < ITERS; t++) {
                if (g_diff[t] == 0) { iters = t + 1; conv = 1; break; }
            }
            out_misc[0] = (float)iters;
            out_misc[1] = (float)conv;
        }
    }
}

// ---------------- launcher ----------------
extern "C" void kernel_launch(void* const* d_in, const int* in_sizes, int n_in,
                              void* d_out, int out_size) {
    const float* input = nullptr;
    const float* est0  = nullptr;
    const float* cb    = nullptr;
    for (int i = 0; i < n_in; i++) {
        if      (in_sizes[i] == B * D)     input = (const float*)d_in[i];
        else if (in_sizes[i] == B * F * D) est0  = (const float*)d_in[i];
        else if (in_sizes[i] == F * M * D) cb    = (const float*)d_in[i];
    }
    if (!input) input = (const float*)d_in[0];
    if (!est0)  est0  = (const float*)d_in[1];
    if (!cb)    cb    = (const float*)d_in[2];
    float* out = (float*)d_out;

    static bool attr_done = false;
    if (!attr_done) {
        cudaFuncSetAttribute(k_mega, cudaFuncAttributeMaxDynamicSharedMemorySize, SMEM_MEGA);
        attr_done = true;
    }

    k_pack_all<<<dim3(F, M / 64), 256>>>(cb, input, est0);
    k_gram2<<<dim3(F, 136), 256>>>();

    // output layout (float32): order (outcome, est, iters, conv)
    const long long n_out = B * F;                 // 256
    const long long n_est = (long long)B * F * D;  // 262144
    long long off_outcome = -1, off_est = -1, off_misc = -1;
    if ((long long)out_size >= n_out + n_est + 2) {
        off_outcome = 0; off_est = n_out; off_misc = n_out + n_est;
    } else if ((long long)out_size == n_est) {
        off_est = 0;
    } else if ((long long)out_size == n_out) {
        off_outcome = 0;
    } else if ((long long)out_size == n_out + n_est) {
        off_outcome = 0; off_est = n_out;
    } else {
        off_outcome = 0;
    }

    k_mega<<<dim3(F, 16, 2), 256, SMEM_MEGA>>>(
        off_outcome >= 0 ? out + off_outcome : nullptr,
        off_est     >= 0 ? out + off_est     : nullptr,
        off_misc    >= 0 ? out + off_misc    : nullptr);
}

// round 13
// speedup vs baseline: 1.6686x; 1.0084x over previous
#include <cuda_runtime.h>
#include <cuda_fp16.h>
#include <cstdint>

#define B 64
#define F 4
#define M 4096
#define D 1024
#define ITERS 15
#define WPD 16   // 64-bit words per D-dim vector
#define WPM 64   // 64-bit words per M-dim vector
#define FINAL_BUF (ITERS & 1)
#define NBLK 128 // persistent blocks; 138KB smem -> 1/SM, 128 < 148 SMs

// dynamic smem layout for k_mega
#define SG_STRIDE   1032                   // halves per row (1024 + 8 pad)
#define SG_BYTES    (64 * SG_STRIDE * 2)   // 132096
#define SNEW_OFF    SG_BYTES
#define SNEW_BYTES  (32 * 17 * 8)          // 4352
#define SBYTES_OFF  (SNEW_OFF + SNEW_BYTES)
#define SMEM_MEGA   (SBYTES_OFF + 32 * 64) // 138496

// ---------------- device scratch (no allocs allowed) ----------------
__device__ unsigned long long g_cb_bits[F][WPD][M];   // codebook bits over d (2 MB)
__device__ unsigned long long g_cbcol[F][D][WPM];     // codebook bits over m (2 MB)
__device__ __half             g_G[F][D][D];           // Gram matrix C^T C, exact even ints (8 MB)
__device__ unsigned long long g_in_bits[B][WPD];
__device__ unsigned long long g_est[2][B][F][WPD];    // double-buffered estimates (bit 1 = -1)
__device__ int                g_key[B * F];           // argmax keys (atomicMax)
__device__ int                g_diff[ITERS];          // per-iteration "changed" flags
__device__ unsigned           g_arrive[NBLK];         // spread-flag barrier: per-block epoch
__device__ unsigned           g_release;              // barrier release epoch

// ---------------- helpers ----------------
__device__ __forceinline__ unsigned long long pack64(const float* p) {
    unsigned long long w = 0ULL;
    #pragma unroll
    for (int t = 0; t < 16; t++) {
        float4 v = reinterpret_cast<const float4*>(p)[t];
        w |= ((unsigned long long)(v.x < 0.f)) << (4 * t + 0);
        w |= ((unsigned long long)(v.y < 0.f)) << (4 * t + 1);
        w |= ((unsigned long long)(v.z < 0.f)) << (4 * t + 2);
        w |= ((unsigned long long)(v.w < 0.f)) << (4 * t + 3);
    }
    return w;
}

__device__ __forceinline__ void mma16816(float* c,
                                         unsigned a0, unsigned a1, unsigned a2, unsigned a3,
                                         unsigned b0, unsigned b1) {
    asm volatile(
        "mma.sync.aligned.m16n8k16.row.col.f32.f16.f16.f32 "
        "{%0,%1,%2,%3}, {%4,%5,%6,%7}, {%8,%9}, {%0,%1,%2,%3};"
        : "+f"(c[0]), "+f"(c[1]), "+f"(c[2]), "+f"(c[3])
        : "r"(a0), "r"(a1), "r"(a2), "r"(a3), "r"(b0), "r"(b1));
}

__device__ __forceinline__ unsigned bits2h2(unsigned bits) {
    return 0x3C003C00u ^ ((bits & 1u) << 15) ^ ((bits & 2u) << 30);
}

// spread-flag epoch barrier: all NBLK blocks co-resident; epoch strictly increasing per call
__device__ __forceinline__ void grid_barrier(int bid, unsigned epoch) {
    __syncthreads();
    if (threadIdx.x == 0) {
        __threadfence();
        atomicExch(&g_arrive[bid], epoch);
    }
    if (bid == 0) {
        if (threadIdx.x < NBLK) {
            while (atomicAdd(&g_arrive[threadIdx.x], 0u) < epoch) {}
        }
        __syncthreads();
        if (threadIdx.x == 0) {
            atomicExch(&g_release, epoch);
        }
    }
    if (threadIdx.x == 0) {
        while (atomicAdd(&g_release, 0u) < epoch) {}
        __threadfence();
    }
    __syncthreads();
}

// ---------------- fused packing: codebook bits + transpose + small inputs ----------------
// grid = (F, M/64), block = 256 (8 warps); each block owns 64 m-rows.
__global__ void __launch_bounds__(256) k_pack_all(const float* __restrict__ cb,
                                                  const float* __restrict__ input,
                                                  const float* __restrict__ est0) {
    __shared__ unsigned long long sm[64][17];   // [m_local][j]
    int f  = blockIdx.x;
    int jm = blockIdx.y;
    int wid = threadIdx.x >> 5, lane = threadIdx.x & 31;

    // small-input packing spread over first 23 blocks of f == 0
    if (f == 0 && jm < 23) {
        int idx = jm * 256 + threadIdx.x;
        if (idx < 1024) {                       // B*WPD
            int b = idx >> 4, j = idx & 15;
            g_in_bits[b][j] = pack64(input + b * D + j * 64);
        } else if (idx < 5120) {                // + B*F*WPD
            int w = idx - 1024;
            int b = w >> 6, ff = (w >> 4) & 3, j = w & 15;
            g_est[0][b][ff][j] = pack64(est0 + (size_t)(b * F + ff) * D + j * 64);
        } else if (idx < 5120 + ITERS) {
            g_diff[idx - 5120] = 0;
        } else if (idx < 5135 + B * F) {
            g_key[idx - 5135] = -1;
        } else if (idx < 5391 + NBLK) {
            g_arrive[idx - 5391] = 0u;
        } else if (idx == 5391 + NBLK) {
            g_release = 0u;
        }
    }

    #pragma unroll
    for (int r = 0; r < 8; r++) {
        int ml = wid * 8 + r;
        int m = jm * 64 + ml;
        const float* row = cb + ((size_t)(f * M + m)) * D;
        // prefetch: 32 independent coalesced loads per thread -> high MLP
        float va[WPD], vb[WPD];
        #pragma unroll
        for (int j = 0; j < WPD; j++) {
            va[j] = row[j * 64 + lane];
            vb[j] = row[j * 64 + 32 + lane];
        }
        #pragma unroll
        for (int j = 0; j < WPD; j++) {
            unsigned lo = __ballot_sync(0xffffffffu, va[j] < 0.f);
            unsigned hi = __ballot_sync(0xffffffffu, vb[j] < 0.f);
            if (lane == 0) {
                unsigned long long w = ((unsigned long long)hi << 32) | lo;
                g_cb_bits[f][j][m] = w;
                sm[ml][j] = w;
            }
        }
    }
    __syncthreads();

    for (int i = 0; i < 128; i++) {
        int d = wid * 128 + i;
        int j = d >> 6, bp = d & 63;
        unsigned lo = __ballot_sync(0xffffffffu,
            (unsigned)((sm[lane][j] >> bp) & 1ULL));
        unsigned hi = __ballot_sync(0xffffffffu,
            (unsigned)((sm[lane + 32][j] >> bp) & 1ULL));
        if (lane == 0)
            g_cbcol[f][d][jm] = ((unsigned long long)hi << 32) | lo;
    }
}

// ---------------- Gram: symmetric 64x64 tiles, 4x4/thread, stride-16 rows ----------------
__global__ void __launch_bounds__(256) k_gram2() {
    __shared__ unsigned long long shX[64][17];
    __shared__ unsigned long long shY[64][17];
    __shared__ __half stage[64][72];

    int f = blockIdx.x;
    int p = blockIdx.y;                 // triangular pair index, 136 per f
    int tx = 0;
    while (p >= 16 - tx) { p -= 16 - tx; tx++; }
    int ty = tx + p;
    int x0 = tx * 64, y0 = ty * 64;

    int tid = threadIdx.x;
    int u = tid >> 4;                   // x base row, rows u+16i
    int v = tid & 15;                   // y base row, rows v+16j

    int acc[4][4];
    #pragma unroll
    for (int i = 0; i < 4; i++)
        #pragma unroll
        for (int j = 0; j < 4; j++) acc[i][j] = 0;

    for (int kc = 0; kc < WPM; kc += 16) {
        #pragma unroll
        for (int r = 0; r < 4; r++) {
            int idx = tid + 256 * r;
            int row = idx >> 4, w = idx & 15;
            shX[row][w] = g_cbcol[f][x0 + row][kc + w];
            shY[row][w] = g_cbcol[f][y0 + row][kc + w];
        }
        __syncthreads();
        #pragma unroll
        for (int w = 0; w < 16; w++) {
            unsigned long long x0v = shX[u     ][w];
            unsigned long long x1v = shX[u + 16][w];
            unsigned long long x2v = shX[u + 32][w];
            unsigned long long x3v = shX[u + 48][w];
            unsigned long long y0v = shY[v     ][w];
            unsigned long long y1v = shY[v + 16][w];
            unsigned long long y2v = shY[v + 32][w];
            unsigned long long y3v = shY[v + 48][w];
            acc[0][0] += __popcll(x0v ^ y0v); acc[0][1] += __popcll(x0v ^ y1v);
            acc[0][2] += __popcll(x0v ^ y2v); acc[0][3] += __popcll(x0v ^ y3v);
            acc[1][0] += __popcll(x1v ^ y0v); acc[1][1] += __popcll(x1v ^ y1v);
            acc[1][2] += __popcll(x1v ^ y2v); acc[1][3] += __popcll(x1v ^ y3v);
            acc[2][0] += __popcll(x2v ^ y0v); acc[2][1] += __popcll(x2v ^ y1v);
            acc[2][2] += __popcll(x2v ^ y2v); acc[2][3] += __popcll(x2v ^ y3v);
            acc[3][0] += __popcll(x3v ^ y0v); acc[3][1] += __popcll(x3v ^ y1v);
            acc[3][2] += __popcll(x3v ^ y2v); acc[3][3] += __popcll(x3v ^ y3v);
        }
        __syncthreads();
    }

    #pragma unroll
    for (int i = 0; i < 4; i++)
        #pragma unroll
        for (int j = 0; j < 4; j++)
            stage[u + 16 * i][v + 16 * j] = __int2half_rn(M - 2 * acc[i][j]);
    __syncthreads();

    #pragma unroll
    for (int r = 0; r < 2; r++) {
        int idx = tid + 256 * r;
        int row = idx >> 3, seg = idx & 7;
        *(uint4*)&g_G[f][x0 + row][y0 + seg * 8] = *(const uint4*)&stage[row][seg * 8];
    }

    if (tx != ty) {
        int r = tid >> 2, qd = tid & 3;
        unsigned wds[8];
        #pragma unroll
        for (int k = 0; k < 8; k++) {
            unsigned short h0 = __half_as_ushort(stage[qd * 16 + 2 * k    ][r]);
            unsigned short h1 = __half_as_ushort(stage[qd * 16 + 2 * k + 1][r]);
            wds[k] = ((unsigned)h1 << 16) | h0;
        }
        uint4 lo = make_uint4(wds[0], wds[1], wds[2], wds[3]);
        uint4 hi = make_uint4(wds[4], wds[5], wds[6], wds[7]);
        *(uint4*)&g_G[f][y0 + r][x0 + qd * 16    ] = lo;
        *(uint4*)&g_G[f][y0 + r][x0 + qd * 16 + 8] = hi;
    }
}

// ---------------- persistent mega: G tile resident in smem, 15 iters + cleanup + outputs ----
// grid = (F, 16, 2) = 128 blocks, block = 256 (8 warps). Tile: 32(B) x 64(d), K = D from smem.
__global__ void __launch_bounds__(256) k_mega(float* __restrict__ out_outcome,
                                              float* __restrict__ out_est,
                                              float* __restrict__ out_misc) {
    extern __shared__ char smem[];
    __half (*sG)[SG_STRIDE] = (__half(*)[SG_STRIDE])smem;
    unsigned long long (*snew)[17] = (unsigned long long(*)[17])(smem + SNEW_OFF);
    unsigned char (*sbytes)[64] = (unsigned char(*)[64])(smem + SBYTES_OFF);

    const int f  = blockIdx.x;
    const int jd = blockIdx.y;
    const int bz = blockIdx.z;
    const int b0 = bz * 32;
    const int bid = f * 32 + jd * 2 + bz;    // linear block id, 0..127
    const int tid = threadIdx.x;
    const int wid = tid >> 5, lane = tid & 31, g = lane >> 2, q = lane & 3;
    const int mrow0 = (wid >> 2) * 16;       // 2 row groups of 16
    const int ncol0 = (wid & 3) * 16;        // 4 col groups of 16
    const int d0 = jd * 64;

    // load this block's G tile (64 d-rows x 1024 k) into smem ONCE
    #pragma unroll
    for (int r = 0; r < 32; r++) {
        int idx = tid + 256 * r;          // 8192 uint4
        int row = idx >> 7, seg = idx & 127;
        *(uint4*)&sG[row][seg * 8] = *(const uint4*)&g_G[f][d0 + row][seg * 8];
    }
    __syncthreads();

    for (int t = 0; t < ITERS; t++) {
        const int rbuf = t & 1, wbuf = rbuf ^ 1;

        // new_est bits: in ^ (xor over all f) ^ est_f
        #pragma unroll
        for (int r = 0; r < 2; r++) {
            int idx = tid + 256 * r;
            int bl = idx >> 4, j = idx & 15;
            int b = b0 + bl;
            unsigned long long tot = g_in_bits[b][j];
            #pragma unroll
            for (int ff = 0; ff < F; ff++) tot ^= g_est[rbuf][b][ff][j];
            snew[bl][j] = tot ^ g_est[rbuf][b][f][j];
        }
        __syncthreads();

        float acc[2][4];
        #pragma unroll
        for (int i = 0; i < 2; i++)
            #pragma unroll
            for (int jj = 0; jj < 4; jj++) acc[i][jj] = 0.f;

        #pragma unroll 4
        for (int wj = 0; wj < 16; wj++) {
            // hoist the per-lane shift: one 64-bit shift per word
            unsigned long long w0 = snew[mrow0 + g][wj] >> (q * 2);
            unsigned long long w1 = snew[mrow0 + 8 + g][wj] >> (q * 2);
            #pragma unroll
            for (int kk = 0; kk < 64; kk += 16) {
                unsigned a0 = bits2h2((unsigned)(w0 >> kk) & 3u);
                unsigned a1 = bits2h2((unsigned)(w1 >> kk) & 3u);
                unsigned a2 = bits2h2((unsigned)(w0 >> (kk + 8)) & 3u);
                unsigned a3 = bits2h2((unsigned)(w1 >> (kk + 8)) & 3u);
                #pragma unroll
                for (int nt = 0; nt < 2; nt++) {
                    unsigned b0v = *(const unsigned*)&sG[ncol0 + nt * 8 + g][wj * 64 + kk + q * 2];
                    unsigned b1v = *(const unsigned*)&sG[ncol0 + nt * 8 + g][wj * 64 + kk + 8 + q * 2];
                    mma16816(acc[nt], a0, a1, a2, a3, b0v, b1v);
                }
            }
        }

        // epilogue: sign bytes
        int r0 = mrow0 + g;
        #pragma unroll
        for (int nt = 0; nt < 2; nt++) {
            int c0 = ncol0 + nt * 8 + q * 2;
            sbytes[r0    ][c0    ] = (unsigned char)(acc[nt][0] < 0.f);
            sbytes[r0    ][c0 + 1] = (unsigned char)(acc[nt][1] < 0.f);
            sbytes[r0 + 8][c0    ] = (unsigned char)(acc[nt][2] < 0.f);
            sbytes[r0 + 8][c0 + 1] = (unsigned char)(acc[nt][3] < 0.f);
        }
        __syncthreads();

        if (tid < 32) {
            const unsigned long long* q8 = (const unsigned long long*)sbytes[tid];
            unsigned long long w = 0ULL;
            #pragma unroll
            for (int s = 0; s < 8; s++) {
                unsigned long long x = q8[s];
                #pragma unroll
                for (int k = 0; k < 8; k++)
                    w |= ((x >> (8 * k)) & 1ULL) << (8 * s + k);
            }
            int b = b0 + tid;
            bool diff = (w != g_est[rbuf][b][f][jd]);
            g_est[wbuf][b][f][jd] = w;
            unsigned bal = __ballot_sync(0xffffffffu, diff);
            if (lane == 0 && bal) atomicOr(&g_diff[t], 1);
        }
        grid_barrier(bid, (unsigned)(t + 1));
    }

    // ---- cleanup: partial argmax over this block's 128-m chunk, all 64 b (reuse sG space) ----
    {
        unsigned long long (*sest)[WPD] = (unsigned long long(*)[WPD])smem;
        #pragma unroll
        for (int r = 0; r < 4; r++) {
            int idx = tid + 256 * r;
            int b = idx >> 4, j = idx & 15;
            sest[b][j] = g_est[FINAL_BUF][b][f][j];
        }
        __syncthreads();

        int m = (jd * 2 + bz) * 128 + (tid & 127);
        int bh = (tid >> 7) * 32;
        for (int bb = 0; bb < 32; bb++) {
            int b = bh + bb;
            int acc = 0;
            #pragma unroll
            for (int j = 0; j < WPD; j++)
                acc += __popcll(g_cb_bits[f][j][m] ^ sest[b][j]);
            int vv = D - 2 * acc;
            int a = vv < 0 ? -vv : vv;
            int key = (a << 12) | (4095 - m);
            #pragma unroll
            for (int s = 16; s > 0; s >>= 1) {
                int o = __shfl_down_sync(0xffffffffu, key, s);
                if (o > key) key = o;
            }
            if (lane == 0) atomicMax(&g_key[b * F + f], key);
        }
    }

    // ---- est output: 2048 floats per block ----
    if (out_est) {
        int blk = (f * 16 + jd) * 2 + bz;
        int base = blk * 2048;
        #pragma unroll
        for (int r = 0; r < 8; r++) {
            int idx = base + tid + 256 * r;    // b*F*D + f*D + d
            int d = idx & (D - 1);
            int ff = (idx >> 10) & 3;
            int b = idx >> 12;
            unsigned long long w = g_est[FINAL_BUF][b][ff][d >> 6];
            out_est[idx] = ((w >> (d & 63)) & 1ULL) ? -1.f : 1.f;
        }
    }

    grid_barrier(bid, (unsigned)(ITERS + 1));

    if (bid == 0) {
        if (out_outcome && tid < B * F)
            out_outcome[tid] = (float)(4095 - (g_key[tid] & 4095));
        if (out_misc && tid == 0) {
            int iters = ITERS, conv = 0;
            for (int t = 0; t < ITERS; t++) {
                if (g_diff[t] == 0) { iters = t + 1; conv = 1; break; }
            }
            out_misc[0] = (float)iters;
            out_misc[1] = (float)conv;
        }
    }
}

// ---------------- launcher ----------------
extern "C" void kernel_launch(void* const* d_in, const int* in_sizes, int n_in,
                              void* d_out, int out_size) {
    const float* input = nullptr;
    const float* est0  = nullptr;
    const float* cb    = nullptr;
    for (int i = 0; i < n_in; i++) {
        if      (in_sizes[i] == B * D)     input = (const float*)d_in[i];
        else if (in_sizes[i] == B * F * D) est0  = (const float*)d_in[i];
        else if (in_sizes[i] == F * M * D) cb    = (const float*)d_in[i];
    }
    if (!input) input = (const float*)d_in[0];
    if (!est0)  est0  = (const float*)d_in[1];
    if (!cb)    cb    = (const float*)d_in[2];
    float* out = (float*)d_out;

    static bool attr_done = false;
    if (!attr_done) {
        cudaFuncSetAttribute(k_mega, cudaFuncAttributeMaxDynamicSharedMemorySize, SMEM_MEGA);
        attr_done = true;
    }

    k_pack_all<<<dim3(F, M / 64), 256>>>(cb, input, est0);
    k_gram2<<<dim3(F, 136), 256>>>();

    // output layout (float32): order (outcome, est, iters, conv)
    const long long n_out = B * F;                 // 256
    const long long n_est = (long long)B * F * D;  // 262144
    long long off_outcome = -1, off_est = -1, off_misc = -1;
    if ((long long)out_size >= n_out + n_est + 2) {
        off_outcome = 0; off_est = n_out; off_misc = n_out + n_est;
    } else if ((long long)out_size == n_est) {
        off_est = 0;
    } else if ((long long)out_size == n_out) {
        off_outcome = 0;
    } else if ((long long)out_size == n_out + n_est) {
        off_outcome = 0; off_est = n_out;
    } else {
        off_outcome = 0;
    }

    k_mega<<<dim3(F, 16, 2), 256, SMEM_MEGA>>>(
        off_outcome >= 0 ? out + off_outcome : nullptr,
        off_est     >= 0 ? out + off_est     : nullptr,
        off_misc    >= 0 ? out + off_misc    : nullptr);
}

// round 14
// speedup vs baseline: 1.6720x; 1.0020x over previous
#include <cuda_runtime.h>
#include <cuda_fp16.h>
#include <cstdint>

#define B 64
#define F 4
#define M 4096
#define D 1024
#define ITERS 15
#define WPD 16   // 64-bit words per D-dim vector
#define WPM 64   // 64-bit words per M-dim vector
#define FINAL_BUF (ITERS & 1)
#define NBLK 128 // persistent blocks; 200KB smem -> 1/SM, 128 < 148 SMs

// dynamic smem layout for k_mega (halves, stride 1032 -> rows rotate 4 banks: LDSM conflict-free)
#define SROW      1032
#define SG_BYTES  (64 * SROW * 2)            // 132096: G tile [64 d][1024 k]
#define SA_OFF    SG_BYTES
#define SA_BYTES  (32 * SROW * 2)            // 66048: new_est halves [32 b][1024 k]
#define SBY_OFF   (SA_OFF + SA_BYTES)        // 198144
#define SMEM_MEGA (SBY_OFF + 32 * 64)        // 200192

// ---------------- device scratch (no allocs allowed) ----------------
__device__ unsigned long long g_cb_bits[F][WPD][M];   // codebook bits over d (2 MB)
__device__ unsigned long long g_cbcol[F][D][WPM];     // codebook bits over m (2 MB)
__device__ __half             g_G[F][D][D];           // Gram matrix C^T C, exact even ints (8 MB)
__device__ unsigned long long g_in_bits[B][WPD];
__device__ unsigned long long g_est[2][B][F][WPD];    // double-buffered estimates (bit 1 = -1)
__device__ int                g_key[B * F];           // argmax keys (atomicMax)
__device__ int                g_diff[ITERS];          // per-iteration "changed" flags
__device__ unsigned           g_arrive[NBLK];         // spread-flag barrier: per-block epoch
__device__ unsigned           g_release;              // barrier release epoch

// ---------------- helpers ----------------
__device__ __forceinline__ unsigned long long pack64(const float* p) {
    unsigned long long w = 0ULL;
    #pragma unroll
    for (int t = 0; t < 16; t++) {
        float4 v = reinterpret_cast<const float4*>(p)[t];
        w |= ((unsigned long long)(v.x < 0.f)) << (4 * t + 0);
        w |= ((unsigned long long)(v.y < 0.f)) << (4 * t + 1);
        w |= ((unsigned long long)(v.z < 0.f)) << (4 * t + 2);
        w |= ((unsigned long long)(v.w < 0.f)) << (4 * t + 3);
    }
    return w;
}

__device__ __forceinline__ void mma16816(float* c,
                                         unsigned a0, unsigned a1, unsigned a2, unsigned a3,
                                         unsigned b0, unsigned b1) {
    asm volatile(
        "mma.sync.aligned.m16n8k16.row.col.f32.f16.f16.f32 "
        "{%0,%1,%2,%3}, {%4,%5,%6,%7}, {%8,%9}, {%0,%1,%2,%3};"
        : "+f"(c[0]), "+f"(c[1]), "+f"(c[2]), "+f"(c[3])
        : "r"(a0), "r"(a1), "r"(a2), "r"(a3), "r"(b0), "r"(b1));
}

__device__ __forceinline__ void ldsm_x4(unsigned& r0, unsigned& r1, unsigned& r2, unsigned& r3,
                                        unsigned addr) {
    asm volatile("ldmatrix.sync.aligned.m8n8.x4.shared.b16 {%0,%1,%2,%3}, [%4];"
                 : "=r"(r0), "=r"(r1), "=r"(r2), "=r"(r3) : "r"(addr));
}

__device__ __forceinline__ void ldsm_x2(unsigned& r0, unsigned& r1, unsigned addr) {
    asm volatile("ldmatrix.sync.aligned.m8n8.x2.shared.b16 {%0,%1}, [%2];"
                 : "=r"(r0), "=r"(r1) : "r"(addr));
}

__device__ __forceinline__ unsigned bits2h2(unsigned bits) {
    return 0x3C003C00u ^ ((bits & 1u) << 15) ^ ((bits & 2u) << 30);
}

// spread-flag epoch barrier: all NBLK blocks co-resident; epoch strictly increasing per call
__device__ __forceinline__ void grid_barrier(int bid, unsigned epoch) {
    __syncthreads();
    if (threadIdx.x == 0) {
        __threadfence();
        atomicExch(&g_arrive[bid], epoch);
    }
    if (bid == 0) {
        if (threadIdx.x < NBLK) {
            while (atomicAdd(&g_arrive[threadIdx.x], 0u) < epoch) {}
        }
        __syncthreads();
        if (threadIdx.x == 0) {
            atomicExch(&g_release, epoch);
        }
    }
    if (threadIdx.x == 0) {
        while (atomicAdd(&g_release, 0u) < epoch) {}
        __threadfence();
    }
    __syncthreads();
}

// ---------------- fused packing: codebook bits + transpose + small inputs ----------------
// grid = (F, M/64), block = 512 (16 warps); each block owns 64 m-rows, each warp 4 rows.
__global__ void __launch_bounds__(512) k_pack_all(const float* __restrict__ cb,
                                                  const float* __restrict__ input,
                                                  const float* __restrict__ est0) {
    __shared__ unsigned long long sm[64][17];   // [m_local][j]
    int f  = blockIdx.x;
    int jm = blockIdx.y;
    int wid = threadIdx.x >> 5, lane = threadIdx.x & 31;

    // small-input packing spread over first 11 blocks of f == 0
    if (f == 0 && jm < 11) {
        int idx = jm * 512 + threadIdx.x;
        if (idx < 1024) {                       // B*WPD
            int b = idx >> 4, j = idx & 15;
            g_in_bits[b][j] = pack64(input + b * D + j * 64);
        } else if (idx < 5120) {                // + B*F*WPD
            int w = idx - 1024;
            int b = w >> 6, ff = (w >> 4) & 3, j = w & 15;
            g_est[0][b][ff][j] = pack64(est0 + (size_t)(b * F + ff) * D + j * 64);
        } else if (idx < 5120 + ITERS) {
            g_diff[idx - 5120] = 0;
        } else if (idx < 5135 + B * F) {
            g_key[idx - 5135] = -1;
        } else if (idx < 5391 + NBLK) {
            g_arrive[idx - 5391] = 0u;
        } else if (idx == 5391 + NBLK) {
            g_release = 0u;
        }
    }

    #pragma unroll
    for (int r = 0; r < 4; r++) {
        int ml = wid * 4 + r;
        int m = jm * 64 + ml;
        const float* row = cb + ((size_t)(f * M + m)) * D;
        float va[WPD], vb[WPD];
        #pragma unroll
        for (int j = 0; j < WPD; j++) {
            va[j] = row[j * 64 + lane];
            vb[j] = row[j * 64 + 32 + lane];
        }
        #pragma unroll
        for (int j = 0; j < WPD; j++) {
            unsigned lo = __ballot_sync(0xffffffffu, va[j] < 0.f);
            unsigned hi = __ballot_sync(0xffffffffu, vb[j] < 0.f);
            if (lane == 0) {
                unsigned long long w = ((unsigned long long)hi << 32) | lo;
                g_cb_bits[f][j][m] = w;
                sm[ml][j] = w;
            }
        }
    }
    __syncthreads();

    // transpose: 16 warps x 64 d each
    for (int i = 0; i < 64; i++) {
        int d = wid * 64 + i;
        int j = d >> 6, bp = d & 63;
        unsigned lo = __ballot_sync(0xffffffffu,
            (unsigned)((sm[lane][j] >> bp) & 1ULL));
        unsigned hi = __ballot_sync(0xffffffffu,
            (unsigned)((sm[lane + 32][j] >> bp) & 1ULL));
        if (lane == 0)
            g_cbcol[f][d][jm] = ((unsigned long long)hi << 32) | lo;
    }
}

// ---------------- Gram: symmetric 64x64 tiles, 4x4/thread, stride-16 rows ----------------
__global__ void __launch_bounds__(256) k_gram2() {
    __shared__ unsigned long long shX[64][17];
    __shared__ unsigned long long shY[64][17];
    __shared__ __half stage[64][72];

    int f = blockIdx.x;
    int p = blockIdx.y;                 // triangular pair index, 136 per f
    int tx = 0;
    while (p >= 16 - tx) { p -= 16 - tx; tx++; }
    int ty = tx + p;
    int x0 = tx * 64, y0 = ty * 64;

    int tid = threadIdx.x;
    int u = tid >> 4;                   // x base row, rows u+16i
    int v = tid & 15;                   // y base row, rows v+16j

    int acc[4][4];
    #pragma unroll
    for (int i = 0; i < 4; i++)
        #pragma unroll
        for (int j = 0; j < 4; j++) acc[i][j] = 0;

    for (int kc = 0; kc < WPM; kc += 16) {
        #pragma unroll
        for (int r = 0; r < 4; r++) {
            int idx = tid + 256 * r;
            int row = idx >> 4, w = idx & 15;
            shX[row][w] = g_cbcol[f][x0 + row][kc + w];
            shY[row][w] = g_cbcol[f][y0 + row][kc + w];
        }
        __syncthreads();
        #pragma unroll
        for (int w = 0; w < 16; w++) {
            unsigned long long x0v = shX[u     ][w];
            unsigned long long x1v = shX[u + 16][w];
            unsigned long long x2v = shX[u + 32][w];
            unsigned long long x3v = shX[u + 48][w];
            unsigned long long y0v = shY[v     ][w];
            unsigned long long y1v = shY[v + 16][w];
            unsigned long long y2v = shY[v + 32][w];
            unsigned long long y3v = shY[v + 48][w];
            acc[0][0] += __popcll(x0v ^ y0v); acc[0][1] += __popcll(x0v ^ y1v);
            acc[0][2] += __popcll(x0v ^ y2v); acc[0][3] += __popcll(x0v ^ y3v);
            acc[1][0] += __popcll(x1v ^ y0v); acc[1][1] += __popcll(x1v ^ y1v);
            acc[1][2] += __popcll(x1v ^ y2v); acc[1][3] += __popcll(x1v ^ y3v);
            acc[2][0] += __popcll(x2v ^ y0v); acc[2][1] += __popcll(x2v ^ y1v);
            acc[2][2] += __popcll(x2v ^ y2v); acc[2][3] += __popcll(x2v ^ y3v);
            acc[3][0] += __popcll(x3v ^ y0v); acc[3][1] += __popcll(x3v ^ y1v);
            acc[3][2] += __popcll(x3v ^ y2v); acc[3][3] += __popcll(x3v ^ y3v);
        }
        __syncthreads();
    }

    #pragma unroll
    for (int i = 0; i < 4; i++)
        #pragma unroll
        for (int j = 0; j < 4; j++)
            stage[u + 16 * i][v + 16 * j] = __int2half_rn(M - 2 * acc[i][j]);
    __syncthreads();

    #pragma unroll
    for (int r = 0; r < 2; r++) {
        int idx = tid + 256 * r;
        int row = idx >> 3, seg = idx & 7;
        *(uint4*)&g_G[f][x0 + row][y0 + seg * 8] = *(const uint4*)&stage[row][seg * 8];
    }

    if (tx != ty) {
        int r = tid >> 2, qd = tid & 3;
        unsigned wds[8];
        #pragma unroll
        for (int k = 0; k < 8; k++) {
            unsigned short h0 = __half_as_ushort(stage[qd * 16 + 2 * k    ][r]);
            unsigned short h1 = __half_as_ushort(stage[qd * 16 + 2 * k + 1][r]);
            wds[k] = ((unsigned)h1 << 16) | h0;
        }
        uint4 lo = make_uint4(wds[0], wds[1], wds[2], wds[3]);
        uint4 hi = make_uint4(wds[4], wds[5], wds[6], wds[7]);
        *(uint4*)&g_G[f][y0 + r][x0 + qd * 16    ] = lo;
        *(uint4*)&g_G[f][y0 + r][x0 + qd * 16 + 8] = hi;
    }
}

// ---------------- persistent mega: G + new_est in smem, LDSM fragments ----------------
// grid = (F, 16, 2) = 128 blocks, block = 256 (8 warps). Tile: 32(B) x 64(d), K = D.
__global__ void __launch_bounds__(256) k_mega(float* __restrict__ out_outcome,
                                              float* __restrict__ out_est,
                                              float* __restrict__ out_misc) {
    extern __shared__ char smem[];
    __half* sG = (__half*)smem;                       // [64][SROW]
    __half* sA = (__half*)(smem + SA_OFF);            // [32][SROW]
    unsigned char (*sbytes)[64] = (unsigned char(*)[64])(smem + SBY_OFF);

    const int f  = blockIdx.x;
    const int jd = blockIdx.y;
    const int bz = blockIdx.z;
    const int b0 = bz * 32;
    const int bid = f * 32 + jd * 2 + bz;    // linear block id, 0..127
    const int tid = threadIdx.x;
    const int wid = tid >> 5, lane = tid & 31, g = lane >> 2, q = lane & 3;
    const int mrow0 = (wid >> 2) * 16;       // 2 row groups of 16
    const int ncol0 = (wid & 3) * 16;        // 4 col groups of 16
    const int d0 = jd * 64;

    // load this block's G tile (64 d-rows x 1024 k) into smem ONCE
    #pragma unroll
    for (int r = 0; r < 32; r++) {
        int idx = tid + 256 * r;          // 8192 uint4
        int row = idx >> 7, seg = idx & 127;
        *(uint4*)&sG[row * SROW + seg * 8] = *(const uint4*)&g_G[f][d0 + row][seg * 8];
    }
    __syncthreads();

    // ldmatrix lane base addresses (bytes, shared space)
    unsigned sG_u32 = (unsigned)__cvta_generic_to_shared(sG);
    unsigned sA_u32 = (unsigned)__cvta_generic_to_shared(sA);
    unsigned addrA = sA_u32 + (mrow0 + (lane & 15)) * (SROW * 2) + ((lane >> 4) * 8) * 2;
    unsigned addrB0 = sG_u32 + (ncol0 + (lane & 7)) * (SROW * 2) + (((lane >> 3) & 1) * 8) * 2;
    unsigned addrB1 = addrB0 + 8 * (SROW * 2);

    for (int t = 0; t < ITERS; t++) {
        const int rbuf = t & 1, wbuf = rbuf ^ 1;

        // expand new_est bits -> +-1 halves in sA (write-swizzled, conflict-free STS.128)
        #pragma unroll
        for (int r = 0; r < 2; r++) {
            int idx = tid + 256 * r;
            int bl = idx >> 4, j = idx & 15;
            int b = b0 + bl;
            unsigned long long tot = g_in_bits[b][j];
            #pragma unroll
            for (int ff = 0; ff < F; ff++) tot ^= g_est[rbuf][b][ff][j];
            unsigned long long w = tot ^ g_est[rbuf][b][f][j];
            __half* rowp = sA + bl * SROW + j * 64;
            #pragma unroll
            for (int s = 0; s < 8; s++) {
                int c = (s + j) & 7;
                unsigned bits = (unsigned)(w >> (8 * c)) & 0xFFu;
                uint4 v;
                v.x = bits2h2(bits & 3u);
                v.y = bits2h2((bits >> 2) & 3u);
                v.z = bits2h2((bits >> 4) & 3u);
                v.w = bits2h2((bits >> 6) & 3u);
                *(uint4*)(rowp + c * 8) = v;
            }
        }
        __syncthreads();

        float acc[2][4];
        #pragma unroll
        for (int i = 0; i < 2; i++)
            #pragma unroll
            for (int jj = 0; jj < 4; jj++) acc[i][jj] = 0.f;

        #pragma unroll 8
        for (int k = 0; k < D; k += 16) {
            unsigned a0, a1, a2, a3, bb0, bb1, bb2, bb3;
            ldsm_x4(a0, a1, a2, a3, addrA + k * 2);
            ldsm_x2(bb0, bb1, addrB0 + k * 2);
            ldsm_x2(bb2, bb3, addrB1 + k * 2);
            mma16816(acc[0], a0, a1, a2, a3, bb0, bb1);
            mma16816(acc[1], a0, a1, a2, a3, bb2, bb3);
        }

        // epilogue: sign bytes
        int r0 = mrow0 + g;
        #pragma unroll
        for (int nt = 0; nt < 2; nt++) {
            int c0 = ncol0 + nt * 8 + q * 2;
            sbytes[r0    ][c0    ] = (unsigned char)(acc[nt][0] < 0.f);
            sbytes[r0    ][c0 + 1] = (unsigned char)(acc[nt][1] < 0.f);
            sbytes[r0 + 8][c0    ] = (unsigned char)(acc[nt][2] < 0.f);
            sbytes[r0 + 8][c0 + 1] = (unsigned char)(acc[nt][3] < 0.f);
        }
        __syncthreads();

        if (tid < 32) {
            const unsigned long long* q8 = (const unsigned long long*)sbytes[tid];
            unsigned long long w = 0ULL;
            #pragma unroll
            for (int s = 0; s < 8; s++) {
                unsigned long long x = q8[s];
                #pragma unroll
                for (int kk = 0; kk < 8; kk++)
                    w |= ((x >> (8 * kk)) & 1ULL) << (8 * s + kk);
            }
            int b = b0 + tid;
            bool diff = (w != g_est[rbuf][b][f][jd]);
            g_est[wbuf][b][f][jd] = w;
            unsigned bal = __ballot_sync(0xffffffffu, diff);
            if (lane == 0 && bal) atomicOr(&g_diff[t], 1);
        }
        grid_barrier(bid, (unsigned)(t + 1));
    }

    // ---- cleanup: partial argmax over this block's 128-m chunk, all 64 b (reuse smem) ----
    {
        unsigned long long (*sest)[WPD] = (unsigned long long(*)[WPD])smem;
        #pragma unroll
        for (int r = 0; r < 4; r++) {
            int idx = tid + 256 * r;
            int b = idx >> 4, j = idx & 15;
            sest[b][j] = g_est[FINAL_BUF][b][f][j];
        }
        __syncthreads();

        int m = (jd * 2 + bz) * 128 + (tid & 127);
        int bh = (tid >> 7) * 32;
        for (int bb = 0; bb < 32; bb++) {
            int b = bh + bb;
            int acc = 0;
            #pragma unroll
            for (int j = 0; j < WPD; j++)
                acc += __popcll(g_cb_bits[f][j][m] ^ sest[b][j]);
            int vv = D - 2 * acc;
            int a = vv < 0 ? -vv : vv;
            int key = (a << 12) | (4095 - m);
            #pragma unroll
            for (int s = 16; s > 0; s >>= 1) {
                int o = __shfl_down_sync(0xffffffffu, key, s);
                if (o > key) key = o;
            }
            if (lane == 0) atomicMax(&g_key[b * F + f], key);
        }
    }

    // ---- est output: 2048 floats per block ----
    if (out_est) {
        int blk = (f * 16 + jd) * 2 + bz;
        int base = blk * 2048;
        #pragma unroll
        for (int r = 0; r < 8; r++) {
            int idx = base + tid + 256 * r;    // b*F*D + f*D + d
            int d = idx & (D - 1);
            int ff = (idx >> 10) & 3;
            int b = idx >> 12;
            unsigned long long w = g_est[FINAL_BUF][b][ff][d >> 6];
            out_est[idx] = ((w >> (d & 63)) & 1ULL) ? -1.f : 1.f;
        }
    }

    grid_barrier(bid, (unsigned)(ITERS + 1));

    if (bid == 0) {
        if (out_outcome && tid < B * F)
            out_outcome[tid] = (float)(4095 - (g_key[tid] & 4095));
        if (out_misc && tid == 0) {
            int iters = ITERS, conv = 0;
            for (int t = 0; t < ITERS; t++) {
                if (g_diff[t] == 0) { iters = t + 1; conv = 1; break; }
            }
            out_misc[0] = (float)iters;
            out_misc[1] = (float)conv;
        }
    }
}

// ---------------- launcher ----------------
extern "C" void kernel_launch(void* const* d_in, const int* in_sizes, int n_in,
                              void* d_out, int out_size) {
    const float* input = nullptr;
    const float* est0  = nullptr;
    const float* cb    = nullptr;
    for (int i = 0; i < n_in; i++) {
        if      (in_sizes[i] == B * D)     input = (const float*)d_in[i];
        else if (in_sizes[i] == B * F * D) est0  = (const float*)d_in[i];
        else if (in_sizes[i] == F * M * D) cb    = (const float*)d_in[i];
    }
    if (!input) input = (const float*)d_in[0];
    if (!est0)  est0  = (const float*)d_in[1];
    if (!cb)    cb    = (const float*)d_in[2];
    float* out = (float*)d_out;

    static bool attr_done = false;
    if (!attr_done) {
        cudaFuncSetAttribute(k_mega, cudaFuncAttributeMaxDynamicSharedMemorySize, SMEM_MEGA);
        attr_done = true;
    }

    k_pack_all<<<dim3(F, M / 64), 512>>>(cb, input, est0);
    k_gram2<<<dim3(F, 136), 256>>>();

    // output layout (float32): order (outcome, est, iters, conv)
    const long long n_out = B * F;                 // 256
    const long long n_est = (long long)B * F * D;  // 262144
    long long off_outcome = -1, off_est = -1, off_misc = -1;
    if ((long long)out_size >= n_out + n_est + 2) {
        off_outcome = 0; off_est = n_out; off_misc = n_out + n_est;
    } else if ((long long)out_size == n_est) {
        off_est = 0;
    } else if ((long long)out_size == n_out) {
        off_outcome = 0;
    } else if ((long long)out_size == n_out + n_est) {
        off_outcome = 0; off_est = n_out;
    } else {
        off_outcome = 0;
    }

    k_mega<<<dim3(F, 16, 2), 256, SMEM_MEGA>>>(
        off_outcome >= 0 ? out + off_outcome : nullptr,
        off_est     >= 0 ? out + off_est     : nullptr,
        off_misc    >= 0 ? out + off_misc    : nullptr);
}